// round 2
// baseline (speedup 1.0000x reference)
#include <cuda_runtime.h>
#include <math.h>

#define HH 128
#define CC 80
#define GG 384
#define MAXN 24576

// ---------------- scratch (static device globals; no runtime allocation) ----
__device__ __align__(256) float g_allf[(size_t)MAXN * 224];          // concat(feat, score, box, origin)
__device__ __align__(256) float g_dec [(size_t)MAXN * 128];          // relu(allf @ feat_W^T + b)
__device__ __align__(256) float g_xp  [(size_t)2 * MAXN * 384];      // per-dir input projections
__device__ __align__(256) float g_hid [(size_t)2 * MAXN * 128];      // forward / backward hidden states
__device__ int g_ucl[CC + 1];                                        // int32-normalized unique_class_len

// ---- K0: normalize unique_class_len (harness may give int32 or int64) ------
__global__ void k0_ucl(const void* __restrict__ ucl_raw) {
    if (threadIdx.x == 0 && blockIdx.x == 0) {
        const int* p32 = (const int*)ucl_raw;
        // int64 little-endian with small positive values => high word of elem1 is 0.
        // int32 data => p32[1] == ucl[1] == first length (>0).
        bool is64 = (p32[1] == 0);
        if (is64) {
            const long long* p64 = (const long long*)ucl_raw;
            for (int i = 0; i <= CC; i++) g_ucl[i] = (int)p64[i];
        } else {
            for (int i = 0; i <= CC; i++) g_ucl[i] = p32[i];
        }
    }
}

// ---------------- tiled fp32 GEMM tile: C[m][n] = act(sum_k A[m][k]*B[n][k] + bias[n])
// BM=64, BN=128, BK=16, 256 threads, 4x8 micro-tile per thread
__device__ __forceinline__ void sgemm_tile(
    const float* __restrict__ A, int lda,
    const float* __restrict__ B, int ldb,
    const float* __restrict__ bias,
    float* __restrict__ Cp, int ldc,
    int M, int Nn, int K, int mBase, int nBase, int relu,
    float* As, float* Bs)
{
    const int tid = threadIdx.x;
    const int tx = tid & 15;      // column group 0..15
    const int ty = tid >> 4;      // row group 0..15
    float acc[4][8];
#pragma unroll
    for (int i = 0; i < 4; i++)
#pragma unroll
        for (int j = 0; j < 8; j++) acc[i][j] = 0.f;

    const int aRow = tid >> 2;          // 0..63
    const int aK4  = (tid & 3) * 4;     // 0,4,8,12
    const int bRow = tid >> 2;          // 0..63, second row at +64
    const int bK4  = (tid & 3) * 4;

    for (int k0 = 0; k0 < K; k0 += 16) {
        {   // A tile load: 64x16 floats, transposed into As[k][m]
            int m = mBase + aRow;
            float4 v = make_float4(0.f, 0.f, 0.f, 0.f);
            if (m < M) v = *reinterpret_cast<const float4*>(A + (size_t)m * lda + k0 + aK4);
            As[(aK4 + 0) * 68 + aRow] = v.x;
            As[(aK4 + 1) * 68 + aRow] = v.y;
            As[(aK4 + 2) * 68 + aRow] = v.z;
            As[(aK4 + 3) * 68 + aRow] = v.w;
        }
#pragma unroll
        for (int r = 0; r < 2; r++) {   // B tile load: 128x16 floats into Bs[k][n]
            int n = nBase + bRow + r * 64;
            float4 v = make_float4(0.f, 0.f, 0.f, 0.f);
            if (n < Nn) v = *reinterpret_cast<const float4*>(B + (size_t)n * ldb + k0 + bK4);
            int nn = bRow + r * 64;
            Bs[(bK4 + 0) * 132 + nn] = v.x;
            Bs[(bK4 + 1) * 132 + nn] = v.y;
            Bs[(bK4 + 2) * 132 + nn] = v.z;
            Bs[(bK4 + 3) * 132 + nn] = v.w;
        }
        __syncthreads();
#pragma unroll
        for (int kk = 0; kk < 16; kk++) {
            float4 ra  = *reinterpret_cast<const float4*>(&As[kk * 68 + ty * 4]);
            float4 rb0 = *reinterpret_cast<const float4*>(&Bs[kk * 132 + tx * 8]);
            float4 rb1 = *reinterpret_cast<const float4*>(&Bs[kk * 132 + tx * 8 + 4]);
            float ar[4] = {ra.x, ra.y, ra.z, ra.w};
            float br[8] = {rb0.x, rb0.y, rb0.z, rb0.w, rb1.x, rb1.y, rb1.z, rb1.w};
#pragma unroll
            for (int i = 0; i < 4; i++)
#pragma unroll
                for (int j = 0; j < 8; j++)
                    acc[i][j] = fmaf(ar[i], br[j], acc[i][j]);
        }
        __syncthreads();
    }
#pragma unroll
    for (int i = 0; i < 4; i++) {
        int m = mBase + ty * 4 + i;
        if (m >= M) continue;
#pragma unroll
        for (int j = 0; j < 8; j++) {
            int n = nBase + tx * 8 + j;
            if (n >= Nn) continue;
            float v = acc[i][j] + bias[n];
            if (relu) v = fmaxf(v, 0.f);
            Cp[(size_t)m * ldc + n] = v;
        }
    }
}

// ---- K1: feat = relu(acb_feature @ appear_W^T + b) fused with allf assembly
__global__ __launch_bounds__(256) void k1_appear(
    const float* __restrict__ feat_in,   // N x 1024
    const float* __restrict__ score,     // N x 32
    const float* __restrict__ box,       // N x 32
    const float* __restrict__ origin,    // N x 32
    const float* __restrict__ W,         // 128 x 1024
    const float* __restrict__ b,         // 128
    int N)
{
    __shared__ float As[16 * 68];
    __shared__ float Bs[16 * 132];
    int mBase = blockIdx.x * 64;
    sgemm_tile(feat_in, 1024, W, 1024, b, g_allf, 224, N, 128, 1024, mBase, 0, 1, As, Bs);
    // epilogue: columns 128..223 of allf = [score | box | origin]
    for (int idx = threadIdx.x; idx < 64 * 96; idx += 256) {
        int r = idx / 96, jc = idx % 96;
        int m = mBase + r;
        if (m < N) {
            float v;
            if (jc < 32)      v = score [(size_t)m * 32 + jc];
            else if (jc < 64) v = box   [(size_t)m * 32 + jc - 32];
            else              v = origin[(size_t)m * 32 + jc - 64];
            g_allf[(size_t)m * 224 + 128 + jc] = v;
        }
    }
}

// ---- K2: dec = relu(allf @ feat_W^T + b)
__global__ __launch_bounds__(256) void k2_dec(
    const float* __restrict__ W,    // 128 x 224
    const float* __restrict__ b,    // 128
    int N)
{
    __shared__ float As[16 * 68];
    __shared__ float Bs[16 * 132];
    int mBase = blockIdx.x * 64;
    sgemm_tile(g_allf, 224, W, 224, b, g_dec, 128, N, 128, 224, mBase, 0, 1, As, Bs);
}

// ---- K3: Xp[d][n][g] = Wih[c][d] @ dec[n] + bih[c][d]  (batched per (class, dir))
__global__ __launch_bounds__(256) void k3_xp(
    const float* __restrict__ Wih,       // C x 2 x 384 x 128
    const float* __restrict__ bih,       // C x 2 x 384
    int N)
{
    int batch = blockIdx.z;              // 0..159
    int c = batch >> 1, d = batch & 1;
    int start = g_ucl[c];
    int len = g_ucl[c + 1] - start;
    int mBase = blockIdx.y * 64;
    if (mBase >= len) return;
    __shared__ float As[16 * 68];
    __shared__ float Bs[16 * 132];
    const float* A  = g_dec + (size_t)start * 128;
    const float* B  = Wih + (size_t)(c * 2 + d) * 384 * 128;
    const float* bb = bih + (size_t)(c * 2 + d) * 384;
    float* Cp = g_xp + (size_t)d * N * 384 + (size_t)start * 384;
    sgemm_tile(A, 128, B, 128, bb, Cp, 384, len, 384, 128, mBase, blockIdx.x * 128, 0, As, Bs);
}

// ---- K4: sequential GRU, one block per (class, dir); Whh rows register-resident
__global__ __launch_bounds__(384, 1) void k4_gru(
    const float* __restrict__ Whh,       // C x 2 x 384 x 128
    const float* __restrict__ bhh,       // C x 2 x 384
    int N)
{
    int bid = blockIdx.x;                    // 0..159
    int c = (CC - 1) - (bid >> 1);           // longest classes first (lengths ascend with c)
    int d = bid & 1;
    int start = g_ucl[c];
    int len = g_ucl[c + 1] - start;
    int g = threadIdx.x;

    __shared__ __align__(16) float h_sm[128];
    __shared__ float pre[256];
    __shared__ float gh3[128];
    __shared__ float x3s[128];

    // Whh row for this gate -> 128 registers
    float4 w4[32];
    {
        const float4* wp = reinterpret_cast<const float4*>(
            Whh + ((size_t)(c * 2 + d) * 384 + g) * 128);
#pragma unroll
        for (int k = 0; k < 32; k++) w4[k] = wp[k];
    }
    float bg = bhh[(size_t)(c * 2 + d) * 384 + g];
    if (g < 128) h_sm[g] = 0.f;
    __syncthreads();

    const float* Xp = g_xp  + (size_t)d * N * 384 + (size_t)start * 384;
    float* Hout     = g_hid + (size_t)d * N * 128 + (size_t)start * 128;

    int j  = (d == 0) ? 0 : len - 1;
    int dj = (d == 0) ? 1 : -1;
    float xg = (len > 0) ? Xp[(size_t)j * 384 + g] : 0.f;

    for (int step = 0; step < len; step++) {
        int jn = j + dj;
        float xn = 0.f;
        if (step + 1 < len) xn = Xp[(size_t)jn * 384 + g];  // prefetch next x

        float a0 = 0.f, a1 = 0.f, a2 = 0.f, a3 = 0.f;
        const float4* h4 = reinterpret_cast<const float4*>(h_sm);
#pragma unroll
        for (int k = 0; k < 32; k++) {
            float4 hv = h4[k];
            float4 wv = w4[k];
            a0 = fmaf(wv.x, hv.x, a0);
            a1 = fmaf(wv.y, hv.y, a1);
            a2 = fmaf(wv.z, hv.z, a2);
            a3 = fmaf(wv.w, hv.w, a3);
        }
        float gh = (a0 + a1) + (a2 + a3) + bg;
        if (g < 256) pre[g] = xg + gh;
        else { gh3[g - 256] = gh; x3s[g - 256] = xg; }
        __syncthreads();
        if (g < 128) {
            float r  = 1.f / (1.f + expf(-pre[g]));
            float z  = 1.f / (1.f + expf(-pre[128 + g]));
            float nn = tanhf(x3s[g] + r * gh3[g]);
            float hp = h_sm[g];
            float h2 = (1.f - z) * nn + z * hp;
            h_sm[g] = h2;
            Hout[(size_t)j * 128 + g] = h2;   // forward: out_f[t]; backward: out_bd[j] directly
        }
        __syncthreads();
        xg = xn;
        j = jn;
    }
}

// ---- K5: out[n] = sigmoid(out_W[:128].hf + out_W[128:].hb + b)  (warp per row)
__global__ __launch_bounds__(256) void k5_out(
    const float* __restrict__ outW, const float* __restrict__ outb,
    float* __restrict__ out, int N)
{
    int t = blockIdx.x * blockDim.x + threadIdx.x;
    int row = t >> 5, lane = t & 31;
    if (row >= N) return;
    const float* hf = g_hid + (size_t)row * 128;
    const float* hb = g_hid + (size_t)N * 128 + (size_t)row * 128;
    float s = 0.f;
#pragma unroll
    for (int k = lane; k < 128; k += 32)
        s += outW[k] * hf[k] + outW[128 + k] * hb[k];
#pragma unroll
    for (int o = 16; o > 0; o >>= 1)
        s += __shfl_down_sync(0xffffffffu, s, o);
    if (lane == 0)
        out[row] = 1.f / (1.f + expf(-(s + outb[0])));
}

extern "C" void kernel_launch(void* const* d_in, const int* in_sizes, int n_in,
                              void* d_out, int out_size)
{
    const float* acb_feat  = (const float*)d_in[3];
    const float* acb_score = (const float*)d_in[4];
    const float* acb_box   = (const float*)d_in[5];
    const float* acb_orig  = (const float*)d_in[6];
    const void*  ucl_raw   = d_in[8];
    const float* appear_W  = (const float*)d_in[9];
    const float* appear_b  = (const float*)d_in[10];
    const float* feat_W    = (const float*)d_in[11];
    const float* feat_b    = (const float*)d_in[12];
    const float* gru_Wih   = (const float*)d_in[13];
    const float* gru_Whh   = (const float*)d_in[14];
    const float* gru_bih   = (const float*)d_in[15];
    const float* gru_bhh   = (const float*)d_in[16];
    const float* out_W     = (const float*)d_in[17];
    const float* out_b     = (const float*)d_in[18];

    int N = in_sizes[3] / 1024;
    if (N > MAXN) N = MAXN;
    int Mtiles = (N + 63) / 64;

    k0_ucl<<<1, 32>>>(ucl_raw);
    k1_appear<<<Mtiles, 256>>>(acb_feat, acb_score, acb_box, acb_orig, appear_W, appear_b, N);
    k2_dec<<<Mtiles, 256>>>(feat_W, feat_b, N);
    dim3 g3(3, 12, 2 * CC);                // n-tiles x m-tiles (len<=768) x (class,dir)
    k3_xp<<<g3, 256>>>(gru_Wih, gru_bih, N);
    k4_gru<<<2 * CC, 384>>>(gru_Whh, gru_bhh, N);
    k5_out<<<(N * 32 + 255) / 256, 256>>>(out_W, out_b, (float*)d_out, N);
}

// round 3
// speedup vs baseline: 1.1549x; 1.1549x over previous
#include <cuda_runtime.h>
#include <math.h>

#define HH 128
#define CC 80
#define MAXN 24576
#define SMS 16 * 136   // smem tile: 16 k-slices x 136-float stride (conflict-free halves)

// ---------------- scratch (static device globals; no runtime allocation) ----
__device__ __align__(256) float g_allf[(size_t)MAXN * 224];
__device__ __align__(256) float g_dec [(size_t)MAXN * 128];
__device__ __align__(256) float g_xp  [(size_t)2 * MAXN * 384];
__device__ __align__(256) float g_hid [(size_t)2 * MAXN * 128];
__device__ int g_ucl[CC + 1];

// ---- K0: normalize unique_class_len (int32 or int64 input) -----------------
__global__ void k0_ucl(const void* __restrict__ ucl_raw) {
    if (threadIdx.x == 0 && blockIdx.x == 0) {
        const int* p32 = (const int*)ucl_raw;
        bool is64 = (p32[1] == 0);   // int64 LE small values -> high word 0
        if (is64) {
            const long long* p64 = (const long long*)ucl_raw;
            for (int i = 0; i <= CC; i++) g_ucl[i] = (int)p64[i];
        } else {
            for (int i = 0; i <= CC; i++) g_ucl[i] = p32[i];
        }
    }
}

// ---------------- GEMM core: BM=128, BN=128, BK=16, 256 thr, 8x8 microtile --
// acc[i][j] = sum_k A[mBase+ty*8+i][k] * B[nBase+tx*8+j][k]
// Caller provides As/Bs (16*136 floats each) and does the epilogue.
__device__ __forceinline__ void sgemm_core(
    const float* __restrict__ A, int lda,
    const float* __restrict__ B, int ldb,   // B already offset to nBase row
    int M, int K, int mBase,
    float* As, float* Bs, float acc[8][8])
{
    const int tid = threadIdx.x;
    const int tx = tid & 15;
    const int ty = tid >> 4;
    const int row = tid >> 1;          // 0..127
    const int k8  = (tid & 1) * 8;     // 0 or 8

#pragma unroll
    for (int i = 0; i < 8; i++)
#pragma unroll
        for (int j = 0; j < 8; j++) acc[i][j] = 0.f;

    for (int k0 = 0; k0 < K; k0 += 16) {
        {   // A tile: 128x16, store transposed As[k][m]
            int m = mBase + row;
            float4 v0 = make_float4(0.f,0.f,0.f,0.f), v1 = v0;
            if (m < M) {
                const float* ap = A + (size_t)m * lda + k0 + k8;
                v0 = *reinterpret_cast<const float4*>(ap);
                v1 = *reinterpret_cast<const float4*>(ap + 4);
            }
            As[(k8+0)*136 + row] = v0.x; As[(k8+1)*136 + row] = v0.y;
            As[(k8+2)*136 + row] = v0.z; As[(k8+3)*136 + row] = v0.w;
            As[(k8+4)*136 + row] = v1.x; As[(k8+5)*136 + row] = v1.y;
            As[(k8+6)*136 + row] = v1.z; As[(k8+7)*136 + row] = v1.w;
        }
        {   // B tile: 128x16 (no n guard: callers use exact-multiple N)
            const float* bp = B + (size_t)row * ldb + k0 + k8;
            float4 v0 = *reinterpret_cast<const float4*>(bp);
            float4 v1 = *reinterpret_cast<const float4*>(bp + 4);
            Bs[(k8+0)*136 + row] = v0.x; Bs[(k8+1)*136 + row] = v0.y;
            Bs[(k8+2)*136 + row] = v0.z; Bs[(k8+3)*136 + row] = v0.w;
            Bs[(k8+4)*136 + row] = v1.x; Bs[(k8+5)*136 + row] = v1.y;
            Bs[(k8+6)*136 + row] = v1.z; Bs[(k8+7)*136 + row] = v1.w;
        }
        __syncthreads();
#pragma unroll
        for (int kk = 0; kk < 16; kk++) {
            float4 ra0 = *reinterpret_cast<const float4*>(&As[kk*136 + ty*8]);
            float4 ra1 = *reinterpret_cast<const float4*>(&As[kk*136 + ty*8 + 4]);
            float4 rb0 = *reinterpret_cast<const float4*>(&Bs[kk*136 + tx*8]);
            float4 rb1 = *reinterpret_cast<const float4*>(&Bs[kk*136 + tx*8 + 4]);
            float ar[8] = {ra0.x,ra0.y,ra0.z,ra0.w, ra1.x,ra1.y,ra1.z,ra1.w};
            float br[8] = {rb0.x,rb0.y,rb0.z,rb0.w, rb1.x,rb1.y,rb1.z,rb1.w};
#pragma unroll
            for (int i = 0; i < 8; i++)
#pragma unroll
                for (int j = 0; j < 8; j++)
                    acc[i][j] = fmaf(ar[i], br[j], acc[i][j]);
        }
        __syncthreads();
    }
}

// ---- K1: feat = relu(acb_feature @ appear_W^T + b), fused allf assembly ----
__global__ __launch_bounds__(256, 2) void k1_appear(
    const float* __restrict__ feat_in,   // N x 1024
    const float* __restrict__ score, const float* __restrict__ box,
    const float* __restrict__ origin,
    const float* __restrict__ W,         // 128 x 1024
    const float* __restrict__ b, int N)
{
    __shared__ float As[SMS], Bs[SMS];
    float acc[8][8];
    int mBase = blockIdx.x * 128;
    sgemm_core(feat_in, 1024, W, 1024, N, 1024, mBase, As, Bs, acc);
    const int tx = threadIdx.x & 15, ty = threadIdx.x >> 4;
#pragma unroll
    for (int i = 0; i < 8; i++) {
        int m = mBase + ty*8 + i;
        if (m >= N) continue;
#pragma unroll
        for (int j = 0; j < 8; j++) {
            int n = tx*8 + j;
            g_allf[(size_t)m*224 + n] = fmaxf(acc[i][j] + b[n], 0.f);
        }
    }
    for (int idx = threadIdx.x; idx < 128 * 96; idx += 256) {
        int r = idx / 96, jc = idx % 96;
        int m = mBase + r;
        if (m < N) {
            float v;
            if (jc < 32)      v = score [(size_t)m*32 + jc];
            else if (jc < 64) v = box   [(size_t)m*32 + jc - 32];
            else              v = origin[(size_t)m*32 + jc - 64];
            g_allf[(size_t)m*224 + 128 + jc] = v;
        }
    }
}

// ---- K2: dec = relu(allf @ feat_W^T + b) -----------------------------------
__global__ __launch_bounds__(256, 2) void k2_dec(
    const float* __restrict__ W, const float* __restrict__ b, int N)
{
    __shared__ float As[SMS], Bs[SMS];
    float acc[8][8];
    int mBase = blockIdx.x * 128;
    sgemm_core(g_allf, 224, W, 224, N, 224, mBase, As, Bs, acc);
    const int tx = threadIdx.x & 15, ty = threadIdx.x >> 4;
#pragma unroll
    for (int i = 0; i < 8; i++) {
        int m = mBase + ty*8 + i;
        if (m >= N) continue;
#pragma unroll
        for (int j = 0; j < 8; j++) {
            int n = tx*8 + j;
            g_dec[(size_t)m*128 + n] = fmaxf(acc[i][j] + b[n], 0.f);
        }
    }
}

// ---- K3: both dirs merged: [len x 128] @ [768 x 128]^T per class -----------
__global__ __launch_bounds__(256, 2) void k3_xp(
    const float* __restrict__ Wih,   // C x (2*384) x 128 contiguous per class
    const float* __restrict__ bih,   // C x 768
    int N)
{
    int c = blockIdx.z;
    int start = g_ucl[c];
    int len = g_ucl[c+1] - start;
    int mBase = blockIdx.y * 128;
    if (mBase >= len) return;
    int nBase = blockIdx.x * 128;    // 0..640
    __shared__ float As[SMS], Bs[SMS];
    float acc[8][8];
    const float* A = g_dec + (size_t)start * 128;
    const float* B = Wih + ((size_t)c * 768 + nBase) * 128;
    const float* bb = bih + (size_t)c * 768;
    sgemm_core(A, 128, B, 128, len, 128, mBase, As, Bs, acc);

    const int tx = threadIdx.x & 15, ty = threadIdx.x >> 4;
    int d  = (nBase >= 384) ? 1 : 0;                 // whole block in one dir
    int nl0 = nBase - d * 384;
    float* dst = g_xp + (size_t)d * N * 384 + (size_t)start * 384;
#pragma unroll
    for (int i = 0; i < 8; i++) {
        int m = mBase + ty*8 + i;
        if (m >= len) continue;
#pragma unroll
        for (int j = 0; j < 8; j++) {
            int n = nBase + tx*8 + j;
            dst[(size_t)m*384 + nl0 + tx*8 + j] = acc[i][j] + bb[n];
        }
    }
}

// ---- K4: sequential GRU, one block per (class, dir), Whh in registers ------
__global__ __launch_bounds__(384, 1) void k4_gru(
    const float* __restrict__ Whh,   // C x 2 x 384 x 128
    const float* __restrict__ bhh,   // C x 2 x 384
    int N)
{
    int bid = blockIdx.x;
    int c = (CC - 1) - (bid >> 1);   // longest classes first
    int d = bid & 1;
    int start = g_ucl[c];
    int len = g_ucl[c+1] - start;
    int g = threadIdx.x;

    __shared__ __align__(16) float h_sm[128];
    __shared__ float pre[256];
    __shared__ float gh3[128];
    __shared__ float x3s[128];

    float4 w4[32];
    {
        const float4* wp = reinterpret_cast<const float4*>(
            Whh + ((size_t)(c*2 + d) * 384 + g) * 128);
#pragma unroll
        for (int k = 0; k < 32; k++) w4[k] = wp[k];
    }
    float bg = bhh[(size_t)(c*2 + d) * 384 + g];
    if (g < 128) h_sm[g] = 0.f;
    __syncthreads();

    const float* Xp = g_xp  + (size_t)d * N * 384 + (size_t)start * 384;
    float* Hout     = g_hid + (size_t)d * N * 128 + (size_t)start * 128;

    int j  = (d == 0) ? 0 : len - 1;
    int dj = (d == 0) ? 1 : -1;
    float xg = (len > 0) ? Xp[(size_t)j * 384 + g] : 0.f;

    for (int step = 0; step < len; step++) {
        int jn = j + dj;
        float xn = 0.f;
        if (step + 1 < len) xn = Xp[(size_t)jn * 384 + g];

        float a0 = 0.f, a1 = 0.f, a2 = 0.f, a3 = 0.f;
        const float4* h4 = reinterpret_cast<const float4*>(h_sm);
#pragma unroll
        for (int k = 0; k < 32; k++) {
            float4 hv = h4[k];
            float4 wv = w4[k];
            a0 = fmaf(wv.x, hv.x, a0);
            a1 = fmaf(wv.y, hv.y, a1);
            a2 = fmaf(wv.z, hv.z, a2);
            a3 = fmaf(wv.w, hv.w, a3);
        }
        float gh = (a0 + a1) + (a2 + a3) + bg;
        if (g < 256) pre[g] = xg + gh;
        else { gh3[g - 256] = gh; x3s[g - 256] = xg; }
        __syncthreads();
        if (g < 128) {
            float r  = __fdividef(1.f, 1.f + __expf(-pre[g]));
            float z  = __fdividef(1.f, 1.f + __expf(-pre[128 + g]));
            float u  = x3s[g] + r * gh3[g];
            u = fminf(fmaxf(u, -15.f), 15.f);
            float e  = __expf(-2.f * u);
            float nn = __fdividef(1.f - e, 1.f + e);
            float hp = h_sm[g];
            float h2 = (1.f - z) * nn + z * hp;
            h_sm[g] = h2;
            Hout[(size_t)j * 128 + g] = h2;
        }
        __syncthreads();
        xg = xn;
        j = jn;
    }
}

// ---- K5: out = sigmoid([hf|hb] . out_W + b), one warp per row --------------
__global__ __launch_bounds__(256) void k5_out(
    const float* __restrict__ outW, const float* __restrict__ outb,
    float* __restrict__ out, int N)
{
    int t = blockIdx.x * blockDim.x + threadIdx.x;
    int row = t >> 5, lane = t & 31;
    if (row >= N) return;
    const float* hf = g_hid + (size_t)row * 128;
    const float* hb = g_hid + (size_t)N * 128 + (size_t)row * 128;
    float s = 0.f;
#pragma unroll
    for (int k = lane; k < 128; k += 32)
        s += outW[k] * hf[k] + outW[128 + k] * hb[k];
#pragma unroll
    for (int o = 16; o > 0; o >>= 1)
        s += __shfl_down_sync(0xffffffffu, s, o);
    if (lane == 0)
        out[row] = __fdividef(1.f, 1.f + __expf(-(s + outb[0])));
}

extern "C" void kernel_launch(void* const* d_in, const int* in_sizes, int n_in,
                              void* d_out, int out_size)
{
    const float* acb_feat  = (const float*)d_in[3];
    const float* acb_score = (const float*)d_in[4];
    const float* acb_box   = (const float*)d_in[5];
    const float* acb_orig  = (const float*)d_in[6];
    const void*  ucl_raw   = d_in[8];
    const float* appear_W  = (const float*)d_in[9];
    const float* appear_b  = (const float*)d_in[10];
    const float* feat_W    = (const float*)d_in[11];
    const float* feat_b    = (const float*)d_in[12];
    const float* gru_Wih   = (const float*)d_in[13];
    const float* gru_Whh   = (const float*)d_in[14];
    const float* gru_bih   = (const float*)d_in[15];
    const float* gru_bhh   = (const float*)d_in[16];
    const float* out_W     = (const float*)d_in[17];
    const float* out_b     = (const float*)d_in[18];

    int N = in_sizes[3] / 1024;
    if (N > MAXN) N = MAXN;
    int Mtiles = (N + 127) / 128;

    k0_ucl<<<1, 32>>>(ucl_raw);
    k1_appear<<<Mtiles, 256>>>(acb_feat, acb_score, acb_box, acb_orig, appear_W, appear_b, N);
    k2_dec<<<Mtiles, 256>>>(feat_W, feat_b, N);
    dim3 g3(6, 4, CC);                 // 768/128 n-tiles x len-tiles x classes
    k3_xp<<<g3, 256>>>(gru_Wih, gru_bih, N);
    k4_gru<<<2 * CC, 384>>>(gru_Whh, gru_bhh, N);
    k5_out<<<(N * 32 + 255) / 256, 256>>>(out_W, out_b, (float*)d_out, N);
}

// round 4
// speedup vs baseline: 1.1999x; 1.0390x over previous
#include <cuda_runtime.h>
#include <math.h>

#define HH 128
#define CC 80
#define MAXN 24576
#define SMS 16 * 136   // smem tile: 16 k-slices x 136-float stride

// ---------------- scratch (static device globals; no runtime allocation) ----
__device__ __align__(256) float g_allf[(size_t)MAXN * 224];
__device__ __align__(256) float g_dec [(size_t)MAXN * 128];
__device__ __align__(256) float g_xp  [(size_t)2 * MAXN * 384];
__device__ __align__(256) float g_hid [(size_t)2 * MAXN * 128];
__device__ int g_ucl[CC + 1];

// ---- K0: normalize unique_class_len (int32 or int64 input) -----------------
__global__ void k0_ucl(const void* __restrict__ ucl_raw) {
    if (threadIdx.x == 0 && blockIdx.x == 0) {
        const int* p32 = (const int*)ucl_raw;
        bool is64 = (p32[1] == 0);   // int64 LE small values -> high word 0
        if (is64) {
            const long long* p64 = (const long long*)ucl_raw;
            for (int i = 0; i <= CC; i++) g_ucl[i] = (int)p64[i];
        } else {
            for (int i = 0; i <= CC; i++) g_ucl[i] = p32[i];
        }
    }
}

// ---------------- GEMM core: BM=128, BN=128, BK=16, 256 thr, 8x8 microtile --
__device__ __forceinline__ void sgemm_core(
    const float* __restrict__ A, int lda,
    const float* __restrict__ B, int ldb,
    int M, int K, int mBase,
    float* As, float* Bs, float acc[8][8])
{
    const int tid = threadIdx.x;
    const int tx = tid & 15;
    const int ty = tid >> 4;
    const int row = tid >> 1;
    const int k8  = (tid & 1) * 8;

#pragma unroll
    for (int i = 0; i < 8; i++)
#pragma unroll
        for (int j = 0; j < 8; j++) acc[i][j] = 0.f;

    for (int k0 = 0; k0 < K; k0 += 16) {
        {
            int m = mBase + row;
            float4 v0 = make_float4(0.f,0.f,0.f,0.f), v1 = v0;
            if (m < M) {
                const float* ap = A + (size_t)m * lda + k0 + k8;
                v0 = *reinterpret_cast<const float4*>(ap);
                v1 = *reinterpret_cast<const float4*>(ap + 4);
            }
            As[(k8+0)*136 + row] = v0.x; As[(k8+1)*136 + row] = v0.y;
            As[(k8+2)*136 + row] = v0.z; As[(k8+3)*136 + row] = v0.w;
            As[(k8+4)*136 + row] = v1.x; As[(k8+5)*136 + row] = v1.y;
            As[(k8+6)*136 + row] = v1.z; As[(k8+7)*136 + row] = v1.w;
        }
        {
            const float* bp = B + (size_t)row * ldb + k0 + k8;
            float4 v0 = *reinterpret_cast<const float4*>(bp);
            float4 v1 = *reinterpret_cast<const float4*>(bp + 4);
            Bs[(k8+0)*136 + row] = v0.x; Bs[(k8+1)*136 + row] = v0.y;
            Bs[(k8+2)*136 + row] = v0.z; Bs[(k8+3)*136 + row] = v0.w;
            Bs[(k8+4)*136 + row] = v1.x; Bs[(k8+5)*136 + row] = v1.y;
            Bs[(k8+6)*136 + row] = v1.z; Bs[(k8+7)*136 + row] = v1.w;
        }
        __syncthreads();
#pragma unroll
        for (int kk = 0; kk < 16; kk++) {
            float4 ra0 = *reinterpret_cast<const float4*>(&As[kk*136 + ty*8]);
            float4 ra1 = *reinterpret_cast<const float4*>(&As[kk*136 + ty*8 + 4]);
            float4 rb0 = *reinterpret_cast<const float4*>(&Bs[kk*136 + tx*8]);
            float4 rb1 = *reinterpret_cast<const float4*>(&Bs[kk*136 + tx*8 + 4]);
            float ar[8] = {ra0.x,ra0.y,ra0.z,ra0.w, ra1.x,ra1.y,ra1.z,ra1.w};
            float br[8] = {rb0.x,rb0.y,rb0.z,rb0.w, rb1.x,rb1.y,rb1.z,rb1.w};
#pragma unroll
            for (int i = 0; i < 8; i++)
#pragma unroll
                for (int j = 0; j < 8; j++)
                    acc[i][j] = fmaf(ar[i], br[j], acc[i][j]);
        }
        __syncthreads();
    }
}

// ---- K1: feat = relu(acb_feature @ appear_W^T + b), fused allf assembly ----
__global__ __launch_bounds__(256, 2) void k1_appear(
    const float* __restrict__ feat_in,
    const float* __restrict__ score, const float* __restrict__ box,
    const float* __restrict__ origin,
    const float* __restrict__ W, const float* __restrict__ b, int N)
{
    __shared__ float As[SMS], Bs[SMS];
    float acc[8][8];
    int mBase = blockIdx.x * 128;
    sgemm_core(feat_in, 1024, W, 1024, N, 1024, mBase, As, Bs, acc);
    const int tx = threadIdx.x & 15, ty = threadIdx.x >> 4;
#pragma unroll
    for (int i = 0; i < 8; i++) {
        int m = mBase + ty*8 + i;
        if (m >= N) continue;
#pragma unroll
        for (int j = 0; j < 8; j++) {
            int n = tx*8 + j;
            g_allf[(size_t)m*224 + n] = fmaxf(acc[i][j] + b[n], 0.f);
        }
    }
    for (int idx = threadIdx.x; idx < 128 * 96; idx += 256) {
        int r = idx / 96, jc = idx % 96;
        int m = mBase + r;
        if (m < N) {
            float v;
            if (jc < 32)      v = score [(size_t)m*32 + jc];
            else if (jc < 64) v = box   [(size_t)m*32 + jc - 32];
            else              v = origin[(size_t)m*32 + jc - 64];
            g_allf[(size_t)m*224 + 128 + jc] = v;
        }
    }
}

// ---- K2: dec = relu(allf @ feat_W^T + b) -----------------------------------
__global__ __launch_bounds__(256, 2) void k2_dec(
    const float* __restrict__ W, const float* __restrict__ b, int N)
{
    __shared__ float As[SMS], Bs[SMS];
    float acc[8][8];
    int mBase = blockIdx.x * 128;
    sgemm_core(g_allf, 224, W, 224, N, 224, mBase, As, Bs, acc);
    const int tx = threadIdx.x & 15, ty = threadIdx.x >> 4;
#pragma unroll
    for (int i = 0; i < 8; i++) {
        int m = mBase + ty*8 + i;
        if (m >= N) continue;
#pragma unroll
        for (int j = 0; j < 8; j++) {
            int n = tx*8 + j;
            g_dec[(size_t)m*128 + n] = fmaxf(acc[i][j] + b[n], 0.f);
        }
    }
}

// ---- K3: both dirs merged: [len x 128] @ [768 x 128]^T per class -----------
__global__ __launch_bounds__(256, 2) void k3_xp(
    const float* __restrict__ Wih, const float* __restrict__ bih, int N)
{
    int c = blockIdx.z;
    int start = g_ucl[c];
    int len = g_ucl[c+1] - start;
    int mBase = blockIdx.y * 128;
    if (mBase >= len) return;
    int nBase = blockIdx.x * 128;
    __shared__ float As[SMS], Bs[SMS];
    float acc[8][8];
    const float* A = g_dec + (size_t)start * 128;
    const float* B = Wih + ((size_t)c * 768 + nBase) * 128;
    const float* bb = bih + (size_t)c * 768;
    sgemm_core(A, 128, B, 128, len, 128, mBase, As, Bs, acc);

    const int tx = threadIdx.x & 15, ty = threadIdx.x >> 4;
    int d  = (nBase >= 384) ? 1 : 0;
    int nl0 = nBase - d * 384;
    float* dst = g_xp + (size_t)d * N * 384 + (size_t)start * 384;
#pragma unroll
    for (int i = 0; i < 8; i++) {
        int m = mBase + ty*8 + i;
        if (m >= len) continue;
#pragma unroll
        for (int j = 0; j < 8; j++) {
            int n = nBase + tx*8 + j;
            dst[(size_t)m*384 + nl0 + tx*8 + j] = acc[i][j] + bb[n];
        }
    }
}

// ---- packed f32x2 FMA (FFMA2 — only reachable via PTX) ---------------------
__device__ __forceinline__ void fma2(unsigned long long& d,
                                     unsigned long long a,
                                     unsigned long long b) {
    asm("fma.rn.f32x2 %0, %1, %2, %0;" : "+l"(d) : "l"(a), "l"(b));
}

// ---- K4: sequential GRU, one block per (class, dir), Whh in registers ------
__global__ __launch_bounds__(384, 1) void k4_gru(
    const float* __restrict__ Whh,   // C x 2 x 384 x 128
    const float* __restrict__ bhh,   // C x 2 x 384
    int N)
{
    int bid = blockIdx.x;
    int c = (CC - 1) - (bid >> 1);   // longest classes first
    int d = bid & 1;
    int start = g_ucl[c];
    int len = g_ucl[c+1] - start;
    int g = threadIdx.x;

    __shared__ __align__(16) float h_sm[128];
    __shared__ float pre[256];
    __shared__ float gh3[128];
    __shared__ float x3s[128];

    // Whh row as 64 packed f32x2 values in registers
    unsigned long long w2[64];
    {
        const ulonglong2* wp = reinterpret_cast<const ulonglong2*>(
            Whh + ((size_t)(c*2 + d) * 384 + g) * 128);
#pragma unroll
        for (int k = 0; k < 32; k++) {
            ulonglong2 v = wp[k];
            w2[2*k]   = v.x;
            w2[2*k+1] = v.y;
        }
    }
    float bg = bhh[(size_t)(c*2 + d) * 384 + g];
    if (g < 128) h_sm[g] = 0.f;
    __syncthreads();

    const float* Xp = g_xp  + (size_t)d * N * 384 + (size_t)start * 384;
    float* Hout     = g_hid + (size_t)d * N * 128 + (size_t)start * 128;

    int j  = (d == 0) ? 0 : len - 1;
    int dj = (d == 0) ? 1 : -1;
    float xg = (len > 0) ? Xp[(size_t)j * 384 + g] : 0.f;

    for (int step = 0; step < len; step++) {
        int jn = j + dj;
        float xn = 0.f;
        if (step + 1 < len) xn = Xp[(size_t)jn * 384 + g];

        unsigned long long a0 = 0ULL, a1 = 0ULL, a2 = 0ULL, a3 = 0ULL;
        const ulonglong2* h2 = reinterpret_cast<const ulonglong2*>(h_sm);
#pragma unroll
        for (int k = 0; k < 32; k += 2) {
            ulonglong2 hv0 = h2[k];
            ulonglong2 hv1 = h2[k+1];
            fma2(a0, w2[2*k],   hv0.x);
            fma2(a1, w2[2*k+1], hv0.y);
            fma2(a2, w2[2*k+2], hv1.x);
            fma2(a3, w2[2*k+3], hv1.y);
        }
        float2 f0 = *reinterpret_cast<float2*>(&a0);
        float2 f1 = *reinterpret_cast<float2*>(&a1);
        float2 f2 = *reinterpret_cast<float2*>(&a2);
        float2 f3 = *reinterpret_cast<float2*>(&a3);
        float gh = ((f0.x + f0.y) + (f1.x + f1.y))
                 + ((f2.x + f2.y) + (f3.x + f3.y)) + bg;

        if (g < 256) pre[g] = xg + gh;
        else { gh3[g - 256] = gh; x3s[g - 256] = xg; }
        __syncthreads();
        if (g < 128) {
            float r  = __fdividef(1.f, 1.f + __expf(-pre[g]));
            float z  = __fdividef(1.f, 1.f + __expf(-pre[128 + g]));
            float u  = x3s[g] + r * gh3[g];
            u = fminf(fmaxf(u, -15.f), 15.f);
            float e  = __expf(-2.f * u);
            float nn = __fdividef(1.f - e, 1.f + e);
            float hp = h_sm[g];
            float h2v = (1.f - z) * nn + z * hp;
            h_sm[g] = h2v;
            Hout[(size_t)j * 128 + g] = h2v;
        }
        __syncthreads();
        xg = xn;
        j = jn;
    }
}

// ---- K5: out = sigmoid([hf|hb] . out_W + b), one warp per row --------------
__global__ __launch_bounds__(256) void k5_out(
    const float* __restrict__ outW, const float* __restrict__ outb,
    float* __restrict__ out, int N)
{
    int t = blockIdx.x * blockDim.x + threadIdx.x;
    int row = t >> 5, lane = t & 31;
    if (row >= N) return;
    const float* hf = g_hid + (size_t)row * 128;
    const float* hb = g_hid + (size_t)N * 128 + (size_t)row * 128;
    float s = 0.f;
#pragma unroll
    for (int k = lane; k < 128; k += 32)
        s += outW[k] * hf[k] + outW[128 + k] * hb[k];
#pragma unroll
    for (int o = 16; o > 0; o >>= 1)
        s += __shfl_down_sync(0xffffffffu, s, o);
    if (lane == 0)
        out[row] = __fdividef(1.f, 1.f + __expf(-(s + outb[0])));
}

extern "C" void kernel_launch(void* const* d_in, const int* in_sizes, int n_in,
                              void* d_out, int out_size)
{
    const float* acb_feat  = (const float*)d_in[3];
    const float* acb_score = (const float*)d_in[4];
    const float* acb_box   = (const float*)d_in[5];
    const float* acb_orig  = (const float*)d_in[6];
    const void*  ucl_raw   = d_in[8];
    const float* appear_W  = (const float*)d_in[9];
    const float* appear_b  = (const float*)d_in[10];
    const float* feat_W    = (const float*)d_in[11];
    const float* feat_b    = (const float*)d_in[12];
    const float* gru_Wih   = (const float*)d_in[13];
    const float* gru_Whh   = (const float*)d_in[14];
    const float* gru_bih   = (const float*)d_in[15];
    const float* gru_bhh   = (const float*)d_in[16];
    const float* out_W     = (const float*)d_in[17];
    const float* out_b     = (const float*)d_in[18];

    int N = in_sizes[3] / 1024;
    if (N > MAXN) N = MAXN;
    int Mtiles = (N + 127) / 128;

    k0_ucl<<<1, 32>>>(ucl_raw);
    k1_appear<<<Mtiles, 256>>>(acb_feat, acb_score, acb_box, acb_orig, appear_W, appear_b, N);
    k2_dec<<<Mtiles, 256>>>(feat_W, feat_b, N);
    dim3 g3(6, 4, CC);
    k3_xp<<<g3, 256>>>(gru_Wih, gru_bih, N);
    k4_gru<<<2 * CC, 384>>>(gru_Whh, gru_bhh, N);
    k5_out<<<(N * 32 + 255) / 256, 256>>>(out_W, out_b, (float*)d_out, N);
}

// round 6
// speedup vs baseline: 1.4549x; 1.2125x over previous
#include <cuda_runtime.h>
#include <cuda_bf16.h>
#include <math.h>
#include <cstdint>

#define HH 128
#define CC 80
#define MAXN 24576
#define SMS 16 * 136
#define ASTRIDE 40   // bf16 elems per smem row (bank-conflict-free for 16816 frag reads)

// ---------------- scratch ----------------------------------------------------
__device__ __align__(256) float g_allf[(size_t)MAXN * 224];
__device__ __align__(256) float g_dec [(size_t)MAXN * 128];
__device__ __align__(256) float g_xp  [(size_t)2 * MAXN * 384];
__device__ __align__(256) float g_hid [(size_t)2 * MAXN * 128];
__device__ int g_ucl[CC + 1];

// ---- K0: normalize unique_class_len (int32 or int64 input) -----------------
__global__ void k0_ucl(const void* __restrict__ ucl_raw) {
    if (threadIdx.x == 0 && blockIdx.x == 0) {
        const int* p32 = (const int*)ucl_raw;
        bool is64 = (p32[1] == 0);
        if (is64) {
            const long long* p64 = (const long long*)ucl_raw;
            for (int i = 0; i <= CC; i++) g_ucl[i] = (int)p64[i];
        } else {
            for (int i = 0; i <= CC; i++) g_ucl[i] = p32[i];
        }
    }
}

// ---- bf16 pack helpers -------------------------------------------------------
__device__ __forceinline__ uint32_t pack_hi(float x, float y) {
    __nv_bfloat16 hx = __float2bfloat16(x), hy = __float2bfloat16(y);
    return ((uint32_t)__bfloat16_as_ushort(hy) << 16) | __bfloat16_as_ushort(hx);
}
__device__ __forceinline__ uint32_t pack_lo(float x, float y) {
    __nv_bfloat16 hx = __float2bfloat16(x), hy = __float2bfloat16(y);
    __nv_bfloat16 lx = __float2bfloat16(x - __bfloat162float(hx));
    __nv_bfloat16 ly = __float2bfloat16(y - __bfloat162float(hy));
    return ((uint32_t)__bfloat16_as_ushort(ly) << 16) | __bfloat16_as_ushort(lx);
}

// ---- m16n8k16 bf16 MMA (arch-neutral PTX; runs on tensor pipe) --------------
__device__ __forceinline__ void mma16816(float c[4], const uint32_t a[4], const uint32_t b[2]) {
    asm volatile(
        "mma.sync.aligned.m16n8k16.row.col.f32.bf16.bf16.f32 "
        "{%0,%1,%2,%3}, {%4,%5,%6,%7}, {%8,%9}, {%0,%1,%2,%3};"
        : "+f"(c[0]), "+f"(c[1]), "+f"(c[2]), "+f"(c[3])
        : "r"(a[0]), "r"(a[1]), "r"(a[2]), "r"(a[3]), "r"(b[0]), "r"(b[1]));
}

// ---- K1 (HMMA): feat = relu(A @ W^T + b) via bf16 hi/lo split (3 MMAs) ------
__global__ __launch_bounds__(256) void k1_appear(
    const float* __restrict__ feat_in,   // N x 1024
    const float* __restrict__ score, const float* __restrict__ box,
    const float* __restrict__ origin,
    const float* __restrict__ W,         // 128 x 1024 fp32
    const float* __restrict__ b, int N)
{
    __shared__ __nv_bfloat16 Ah[128 * ASTRIDE], Al[128 * ASTRIDE];
    __shared__ __nv_bfloat16 Wh[128 * ASTRIDE], Wl[128 * ASTRIDE];

    const int tid  = threadIdx.x;
    const int w    = tid >> 5;
    const int lane = tid & 31;
    const int gid  = lane >> 2;       // 0..7
    const int tig  = lane & 3;        // 0..3
    const int wm   = w & 3;           // 4 m-warps (32 rows each)
    const int wn   = w >> 2;          // 2 n-warps (64 cols each)
    const int mBase = blockIdx.x * 128;

    float acc[2][8][4];
#pragma unroll
    for (int i = 0; i < 2; i++)
#pragma unroll
        for (int j = 0; j < 8; j++)
#pragma unroll
            for (int q = 0; q < 4; q++) acc[i][j][q] = 0.f;

    for (int k0 = 0; k0 < 1024; k0 += 32) {
        __syncthreads();   // protect prior-iter frag reads
        // stage A: 128 rows x 32 cols fp32 -> bf16 hi/lo
#pragma unroll
        for (int it = 0; it < 4; it++) {
            int idx = tid + it * 256;         // 0..1023 float4 slots
            int r  = idx >> 3;
            int c4 = (idx & 7) * 4;
            int m = mBase + r;
            float4 v = make_float4(0.f, 0.f, 0.f, 0.f);
            if (m < N) v = *reinterpret_cast<const float4*>(feat_in + (size_t)m * 1024 + k0 + c4);
            int o = r * ASTRIDE + c4;
            *reinterpret_cast<uint32_t*>(&Ah[o])     = pack_hi(v.x, v.y);
            *reinterpret_cast<uint32_t*>(&Ah[o + 2]) = pack_hi(v.z, v.w);
            *reinterpret_cast<uint32_t*>(&Al[o])     = pack_lo(v.x, v.y);
            *reinterpret_cast<uint32_t*>(&Al[o + 2]) = pack_lo(v.z, v.w);
        }
        // stage W: 128 rows x 32 cols
#pragma unroll
        for (int it = 0; it < 4; it++) {
            int idx = tid + it * 256;
            int r  = idx >> 3;
            int c4 = (idx & 7) * 4;
            float4 v = *reinterpret_cast<const float4*>(W + (size_t)r * 1024 + k0 + c4);
            int o = r * ASTRIDE + c4;
            *reinterpret_cast<uint32_t*>(&Wh[o])     = pack_hi(v.x, v.y);
            *reinterpret_cast<uint32_t*>(&Wh[o + 2]) = pack_hi(v.z, v.w);
            *reinterpret_cast<uint32_t*>(&Wl[o])     = pack_lo(v.x, v.y);
            *reinterpret_cast<uint32_t*>(&Wl[o + 2]) = pack_lo(v.z, v.w);
        }
        __syncthreads();

#pragma unroll
        for (int ks = 0; ks < 32; ks += 16) {
            uint32_t ah[2][4], al[2][4];
#pragma unroll
            for (int mf = 0; mf < 2; mf++) {
                int m0 = wm * 32 + mf * 16;
                int kc = ks + tig * 2;
                ah[mf][0] = *reinterpret_cast<const uint32_t*>(&Ah[(m0 + gid)     * ASTRIDE + kc]);
                ah[mf][1] = *reinterpret_cast<const uint32_t*>(&Ah[(m0 + gid + 8) * ASTRIDE + kc]);
                ah[mf][2] = *reinterpret_cast<const uint32_t*>(&Ah[(m0 + gid)     * ASTRIDE + kc + 8]);
                ah[mf][3] = *reinterpret_cast<const uint32_t*>(&Ah[(m0 + gid + 8) * ASTRIDE + kc + 8]);
                al[mf][0] = *reinterpret_cast<const uint32_t*>(&Al[(m0 + gid)     * ASTRIDE + kc]);
                al[mf][1] = *reinterpret_cast<const uint32_t*>(&Al[(m0 + gid + 8) * ASTRIDE + kc]);
                al[mf][2] = *reinterpret_cast<const uint32_t*>(&Al[(m0 + gid)     * ASTRIDE + kc + 8]);
                al[mf][3] = *reinterpret_cast<const uint32_t*>(&Al[(m0 + gid + 8) * ASTRIDE + kc + 8]);
            }
            uint32_t bh[8][2], bl[8][2];
#pragma unroll
            for (int nf = 0; nf < 8; nf++) {
                int n0 = wn * 64 + nf * 8;
                int kc = ks + tig * 2;
                bh[nf][0] = *reinterpret_cast<const uint32_t*>(&Wh[(n0 + gid) * ASTRIDE + kc]);
                bh[nf][1] = *reinterpret_cast<const uint32_t*>(&Wh[(n0 + gid) * ASTRIDE + kc + 8]);
                bl[nf][0] = *reinterpret_cast<const uint32_t*>(&Wl[(n0 + gid) * ASTRIDE + kc]);
                bl[nf][1] = *reinterpret_cast<const uint32_t*>(&Wl[(n0 + gid) * ASTRIDE + kc + 8]);
            }
#pragma unroll
            for (int mf = 0; mf < 2; mf++)
#pragma unroll
                for (int nf = 0; nf < 8; nf++) {
                    mma16816(acc[mf][nf], ah[mf], bh[nf]);   // hi*hi
                    mma16816(acc[mf][nf], ah[mf], bl[nf]);   // hi*lo
                    mma16816(acc[mf][nf], al[mf], bh[nf]);   // lo*hi
                }
        }
    }

    // epilogue: bias + relu, write to g_allf cols [0,128)
#pragma unroll
    for (int mf = 0; mf < 2; mf++) {
#pragma unroll
        for (int nf = 0; nf < 8; nf++) {
            int m0 = mBase + wm * 32 + mf * 16 + gid;
            int n0 = wn * 64 + nf * 8 + tig * 2;
            if (m0 < N) {
                g_allf[(size_t)m0 * 224 + n0]     = fmaxf(acc[mf][nf][0] + b[n0],     0.f);
                g_allf[(size_t)m0 * 224 + n0 + 1] = fmaxf(acc[mf][nf][1] + b[n0 + 1], 0.f);
            }
            if (m0 + 8 < N) {
                g_allf[(size_t)(m0 + 8) * 224 + n0]     = fmaxf(acc[mf][nf][2] + b[n0],     0.f);
                g_allf[(size_t)(m0 + 8) * 224 + n0 + 1] = fmaxf(acc[mf][nf][3] + b[n0 + 1], 0.f);
            }
        }
    }
    // extra 96 cols of allf
    for (int idx = tid; idx < 128 * 96; idx += 256) {
        int r = idx / 96, jc = idx % 96;
        int m = mBase + r;
        if (m < N) {
            float v;
            if (jc < 32)      v = score [(size_t)m*32 + jc];
            else if (jc < 64) v = box   [(size_t)m*32 + jc - 32];
            else              v = origin[(size_t)m*32 + jc - 64];
            g_allf[(size_t)m*224 + 128 + jc] = v;
        }
    }
}

// ---------------- SIMT GEMM core (used by k2/k3) ------------------------------
__device__ __forceinline__ void sgemm_core(
    const float* __restrict__ A, int lda,
    const float* __restrict__ B, int ldb,
    int M, int K, int mBase,
    float* As, float* Bs, float acc[8][8])
{
    const int tid = threadIdx.x;
    const int tx = tid & 15;
    const int ty = tid >> 4;
    const int row = tid >> 1;
    const int k8  = (tid & 1) * 8;

#pragma unroll
    for (int i = 0; i < 8; i++)
#pragma unroll
        for (int j = 0; j < 8; j++) acc[i][j] = 0.f;

    for (int k0 = 0; k0 < K; k0 += 16) {
        {
            int m = mBase + row;
            float4 v0 = make_float4(0.f,0.f,0.f,0.f), v1 = v0;
            if (m < M) {
                const float* ap = A + (size_t)m * lda + k0 + k8;
                v0 = *reinterpret_cast<const float4*>(ap);
                v1 = *reinterpret_cast<const float4*>(ap + 4);
            }
            As[(k8+0)*136 + row] = v0.x; As[(k8+1)*136 + row] = v0.y;
            As[(k8+2)*136 + row] = v0.z; As[(k8+3)*136 + row] = v0.w;
            As[(k8+4)*136 + row] = v1.x; As[(k8+5)*136 + row] = v1.y;
            As[(k8+6)*136 + row] = v1.z; As[(k8+7)*136 + row] = v1.w;
        }
        {
            const float* bp = B + (size_t)row * ldb + k0 + k8;
            float4 v0 = *reinterpret_cast<const float4*>(bp);
            float4 v1 = *reinterpret_cast<const float4*>(bp + 4);
            Bs[(k8+0)*136 + row] = v0.x; Bs[(k8+1)*136 + row] = v0.y;
            Bs[(k8+2)*136 + row] = v0.z; Bs[(k8+3)*136 + row] = v0.w;
            Bs[(k8+4)*136 + row] = v1.x; Bs[(k8+5)*136 + row] = v1.y;
            Bs[(k8+6)*136 + row] = v1.z; Bs[(k8+7)*136 + row] = v1.w;
        }
        __syncthreads();
#pragma unroll
        for (int kk = 0; kk < 16; kk++) {
            float4 ra0 = *reinterpret_cast<const float4*>(&As[kk*136 + ty*8]);
            float4 ra1 = *reinterpret_cast<const float4*>(&As[kk*136 + ty*8 + 4]);
            float4 rb0 = *reinterpret_cast<const float4*>(&Bs[kk*136 + tx*8]);
            float4 rb1 = *reinterpret_cast<const float4*>(&Bs[kk*136 + tx*8 + 4]);
            float ar[8] = {ra0.x,ra0.y,ra0.z,ra0.w, ra1.x,ra1.y,ra1.z,ra1.w};
            float br[8] = {rb0.x,rb0.y,rb0.z,rb0.w, rb1.x,rb1.y,rb1.z,rb1.w};
#pragma unroll
            for (int i = 0; i < 8; i++)
#pragma unroll
                for (int j = 0; j < 8; j++)
                    acc[i][j] = fmaf(ar[i], br[j], acc[i][j]);
        }
        __syncthreads();
    }
}

// ---- K2: dec = relu(allf @ feat_W^T + b) -----------------------------------
__global__ __launch_bounds__(256, 2) void k2_dec(
    const float* __restrict__ W, const float* __restrict__ b, int N)
{
    __shared__ float As[SMS], Bs[SMS];
    float acc[8][8];
    int mBase = blockIdx.x * 128;
    sgemm_core(g_allf, 224, W, 224, N, 224, mBase, As, Bs, acc);
    const int tx = threadIdx.x & 15, ty = threadIdx.x >> 4;
#pragma unroll
    for (int i = 0; i < 8; i++) {
        int m = mBase + ty*8 + i;
        if (m >= N) continue;
#pragma unroll
        for (int j = 0; j < 8; j++) {
            int n = tx*8 + j;
            g_dec[(size_t)m*128 + n] = fmaxf(acc[i][j] + b[n], 0.f);
        }
    }
}

// ---- K3: both dirs merged: [len x 128] @ [768 x 128]^T per class -----------
__global__ __launch_bounds__(256, 2) void k3_xp(
    const float* __restrict__ Wih, const float* __restrict__ bih, int N)
{
    int c = blockIdx.z;
    int start = g_ucl[c];
    int len = g_ucl[c+1] - start;
    int mBase = blockIdx.y * 128;
    if (mBase >= len) return;
    int nBase = blockIdx.x * 128;
    __shared__ float As[SMS], Bs[SMS];
    float acc[8][8];
    const float* A = g_dec + (size_t)start * 128;
    const float* B = Wih + ((size_t)c * 768 + nBase) * 128;
    const float* bb = bih + (size_t)c * 768;
    sgemm_core(A, 128, B, 128, len, 128, mBase, As, Bs, acc);

    const int tx = threadIdx.x & 15, ty = threadIdx.x >> 4;
    int d  = (nBase >= 384) ? 1 : 0;
    int nl0 = nBase - d * 384;
    float* dst = g_xp + (size_t)d * N * 384 + (size_t)start * 384;
#pragma unroll
    for (int i = 0; i < 8; i++) {
        int m = mBase + ty*8 + i;
        if (m >= len) continue;
#pragma unroll
        for (int j = 0; j < 8; j++) {
            int n = nBase + tx*8 + j;
            dst[(size_t)m*384 + nl0 + tx*8 + j] = acc[i][j] + bb[n];
        }
    }
}

// ---- packed f32x2 FMA ------------------------------------------------------
__device__ __forceinline__ void fma2(unsigned long long& d,
                                     unsigned long long a,
                                     unsigned long long b) {
    asm("fma.rn.f32x2 %0, %1, %2, %0;" : "+l"(d) : "l"(a), "l"(b));
}

// ---- K4: sequential GRU, one block per (class, dir), Whh in registers ------
__global__ __launch_bounds__(384, 1) void k4_gru(
    const float* __restrict__ Whh, const float* __restrict__ bhh, int N)
{
    int bid = blockIdx.x;
    int c = (CC - 1) - (bid >> 1);
    int d = bid & 1;
    int start = g_ucl[c];
    int len = g_ucl[c+1] - start;
    int g = threadIdx.x;

    __shared__ __align__(16) float h_sm[128];
    __shared__ float pre[256];
    __shared__ float gh3[128];
    __shared__ float x3s[128];

    unsigned long long w2[64];
    {
        const ulonglong2* wp = reinterpret_cast<const ulonglong2*>(
            Whh + ((size_t)(c*2 + d) * 384 + g) * 128);
#pragma unroll
        for (int k = 0; k < 32; k++) {
            ulonglong2 v = wp[k];
            w2[2*k]   = v.x;
            w2[2*k+1] = v.y;
        }
    }
    float bg = bhh[(size_t)(c*2 + d) * 384 + g];
    if (g < 128) h_sm[g] = 0.f;
    __syncthreads();

    const float* Xp = g_xp  + (size_t)d * N * 384 + (size_t)start * 384;
    float* Hout     = g_hid + (size_t)d * N * 128 + (size_t)start * 128;

    int j  = (d == 0) ? 0 : len - 1;
    int dj = (d == 0) ? 1 : -1;
    float xg = (len > 0) ? Xp[(size_t)j * 384 + g] : 0.f;

    for (int step = 0; step < len; step++) {
        int jn = j + dj;
        float xn = 0.f;
        if (step + 1 < len) xn = Xp[(size_t)jn * 384 + g];

        unsigned long long a0 = 0ULL, a1 = 0ULL, a2 = 0ULL, a3 = 0ULL;
        const ulonglong2* h2 = reinterpret_cast<const ulonglong2*>(h_sm);
#pragma unroll
        for (int k = 0; k < 32; k += 2) {
            ulonglong2 hv0 = h2[k];
            ulonglong2 hv1 = h2[k+1];
            fma2(a0, w2[2*k],   hv0.x);
            fma2(a1, w2[2*k+1], hv0.y);
            fma2(a2, w2[2*k+2], hv1.x);
            fma2(a3, w2[2*k+3], hv1.y);
        }
        float2 f0 = *reinterpret_cast<float2*>(&a0);
        float2 f1 = *reinterpret_cast<float2*>(&a1);
        float2 f2 = *reinterpret_cast<float2*>(&a2);
        float2 f3 = *reinterpret_cast<float2*>(&a3);
        float gh = ((f0.x + f0.y) + (f1.x + f1.y))
                 + ((f2.x + f2.y) + (f3.x + f3.y)) + bg;

        if (g < 256) pre[g] = xg + gh;
        else { gh3[g - 256] = gh; x3s[g - 256] = xg; }
        __syncthreads();
        if (g < 128) {
            float r  = __fdividef(1.f, 1.f + __expf(-pre[g]));
            float z  = __fdividef(1.f, 1.f + __expf(-pre[128 + g]));
            float u  = x3s[g] + r * gh3[g];
            u = fminf(fmaxf(u, -15.f), 15.f);
            float e  = __expf(-2.f * u);
            float nn = __fdividef(1.f - e, 1.f + e);
            float hp = h_sm[g];
            float h2v = (1.f - z) * nn + z * hp;
            h_sm[g] = h2v;
            Hout[(size_t)j * 128 + g] = h2v;
        }
        __syncthreads();
        xg = xn;
        j = jn;
    }
}

// ---- K5: out = sigmoid([hf|hb] . out_W + b) --------------------------------
__global__ __launch_bounds__(256) void k5_out(
    const float* __restrict__ outW, const float* __restrict__ outb,
    float* __restrict__ out, int N)
{
    int t = blockIdx.x * blockDim.x + threadIdx.x;
    int row = t >> 5, lane = t & 31;
    if (row >= N) return;
    const float* hf = g_hid + (size_t)row * 128;
    const float* hb = g_hid + (size_t)N * 128 + (size_t)row * 128;
    float s = 0.f;
#pragma unroll
    for (int k = lane; k < 128; k += 32)
        s += outW[k] * hf[k] + outW[128 + k] * hb[k];
#pragma unroll
    for (int o = 16; o > 0; o >>= 1)
        s += __shfl_down_sync(0xffffffffu, s, o);
    if (lane == 0)
        out[row] = __fdividef(1.f, 1.f + __expf(-(s + outb[0])));
}

extern "C" void kernel_launch(void* const* d_in, const int* in_sizes, int n_in,
                              void* d_out, int out_size)
{
    const float* acb_feat  = (const float*)d_in[3];
    const float* acb_score = (const float*)d_in[4];
    const float* acb_box   = (const float*)d_in[5];
    const float* acb_orig  = (const float*)d_in[6];
    const void*  ucl_raw   = d_in[8];
    const float* appear_W  = (const float*)d_in[9];
    const float* appear_b  = (const float*)d_in[10];
    const float* feat_W    = (const float*)d_in[11];
    const float* feat_b    = (const float*)d_in[12];
    const float* gru_Wih   = (const float*)d_in[13];
    const float* gru_Whh   = (const float*)d_in[14];
    const float* gru_bih   = (const float*)d_in[15];
    const float* gru_bhh   = (const float*)d_in[16];
    const float* out_W     = (const float*)d_in[17];
    const float* out_b     = (const float*)d_in[18];

    int N = in_sizes[3] / 1024;
    if (N > MAXN) N = MAXN;
    int Mtiles = (N + 127) / 128;

    k0_ucl<<<1, 32>>>(ucl_raw);
    k1_appear<<<Mtiles, 256>>>(acb_feat, acb_score, acb_box, acb_orig,
                               appear_W, appear_b, N);
    k2_dec<<<Mtiles, 256>>>(feat_W, feat_b, N);
    dim3 g3(6, 4, CC);
    k3_xp<<<g3, 256>>>(gru_Wih, gru_bih, N);
    k4_gru<<<2 * CC, 384>>>(gru_Whh, gru_bhh, N);
    k5_out<<<(N * 32 + 255) / 256, 256>>>(out_W, out_b, (float*)d_out, N);
}

// round 7
// speedup vs baseline: 1.4766x; 1.0149x over previous
#include <cuda_runtime.h>
#include <cuda_bf16.h>
#include <math.h>
#include <cstdint>

#define HH 128
#define CC 80
#define MAXN 24576
#define ASTRIDE 40   // bf16 elems per smem row (bank-conflict-free for 16816 frag reads)

// ---------------- scratch ----------------------------------------------------
__device__ __align__(256) float g_allf[(size_t)MAXN * 224];
__device__ __align__(256) float g_dec [(size_t)MAXN * 128];
__device__ __align__(256) float g_xp  [(size_t)2 * MAXN * 384];
__device__ __align__(256) float g_hid [(size_t)2 * MAXN * 128];
__device__ int g_ucl[CC + 1];

// ---- K0: normalize unique_class_len (int32 or int64 input) -----------------
__global__ void k0_ucl(const void* __restrict__ ucl_raw) {
    if (threadIdx.x == 0 && blockIdx.x == 0) {
        const int* p32 = (const int*)ucl_raw;
        bool is64 = (p32[1] == 0);
        if (is64) {
            const long long* p64 = (const long long*)ucl_raw;
            for (int i = 0; i <= CC; i++) g_ucl[i] = (int)p64[i];
        } else {
            for (int i = 0; i <= CC; i++) g_ucl[i] = p32[i];
        }
    }
}

// ---- bf16 pack helpers -------------------------------------------------------
__device__ __forceinline__ uint32_t pack_hi(float x, float y) {
    __nv_bfloat16 hx = __float2bfloat16(x), hy = __float2bfloat16(y);
    return ((uint32_t)__bfloat16_as_ushort(hy) << 16) | __bfloat16_as_ushort(hx);
}
__device__ __forceinline__ uint32_t pack_lo(float x, float y) {
    __nv_bfloat16 hx = __float2bfloat16(x), hy = __float2bfloat16(y);
    __nv_bfloat16 lx = __float2bfloat16(x - __bfloat162float(hx));
    __nv_bfloat16 ly = __float2bfloat16(y - __bfloat162float(hy));
    return ((uint32_t)__bfloat16_as_ushort(ly) << 16) | __bfloat16_as_ushort(lx);
}

// ---- m16n8k16 bf16 MMA (arch-neutral PTX; runs on tensor pipe) --------------
__device__ __forceinline__ void mma16816(float c[4], const uint32_t a[4], const uint32_t b[2]) {
    asm volatile(
        "mma.sync.aligned.m16n8k16.row.col.f32.bf16.bf16.f32 "
        "{%0,%1,%2,%3}, {%4,%5,%6,%7}, {%8,%9}, {%0,%1,%2,%3};"
        : "+f"(c[0]), "+f"(c[1]), "+f"(c[2]), "+f"(c[3])
        : "r"(a[0]), "r"(a[1]), "r"(a[2]), "r"(a[3]), "r"(b[0]), "r"(b[1]));
}

// ---- shared HMMA 128x128 tile core (bf16 hi/lo split, fp32 acc) --------------
// At: tile base (row 0 of this m-tile), rows r valid iff r < mValid.
// Bt: 128 rows, always valid. KTOT multiple of 32.
__device__ __forceinline__ void hmma_tile(
    const float* __restrict__ At, int lda, int mValid,
    const float* __restrict__ Bt, int ldb, int KTOT,
    __nv_bfloat16* Ah, __nv_bfloat16* Al,
    __nv_bfloat16* Wh, __nv_bfloat16* Wl,
    float acc[2][8][4])
{
    const int tid  = threadIdx.x;
    const int w    = tid >> 5;
    const int lane = tid & 31;
    const int gid  = lane >> 2;
    const int tig  = lane & 3;
    const int wm   = w & 3;
    const int wn   = w >> 2;

#pragma unroll
    for (int i = 0; i < 2; i++)
#pragma unroll
        for (int j = 0; j < 8; j++)
#pragma unroll
            for (int q = 0; q < 4; q++) acc[i][j][q] = 0.f;

    for (int k0 = 0; k0 < KTOT; k0 += 32) {
        __syncthreads();
#pragma unroll
        for (int it = 0; it < 4; it++) {
            int idx = tid + it * 256;
            int r  = idx >> 3;
            int c4 = (idx & 7) * 4;
            float4 v = make_float4(0.f, 0.f, 0.f, 0.f);
            if (r < mValid) v = *reinterpret_cast<const float4*>(At + (size_t)r * lda + k0 + c4);
            int o = r * ASTRIDE + c4;
            *reinterpret_cast<uint32_t*>(&Ah[o])     = pack_hi(v.x, v.y);
            *reinterpret_cast<uint32_t*>(&Ah[o + 2]) = pack_hi(v.z, v.w);
            *reinterpret_cast<uint32_t*>(&Al[o])     = pack_lo(v.x, v.y);
            *reinterpret_cast<uint32_t*>(&Al[o + 2]) = pack_lo(v.z, v.w);
        }
#pragma unroll
        for (int it = 0; it < 4; it++) {
            int idx = tid + it * 256;
            int r  = idx >> 3;
            int c4 = (idx & 7) * 4;
            float4 v = *reinterpret_cast<const float4*>(Bt + (size_t)r * ldb + k0 + c4);
            int o = r * ASTRIDE + c4;
            *reinterpret_cast<uint32_t*>(&Wh[o])     = pack_hi(v.x, v.y);
            *reinterpret_cast<uint32_t*>(&Wh[o + 2]) = pack_hi(v.z, v.w);
            *reinterpret_cast<uint32_t*>(&Wl[o])     = pack_lo(v.x, v.y);
            *reinterpret_cast<uint32_t*>(&Wl[o + 2]) = pack_lo(v.z, v.w);
        }
        __syncthreads();

#pragma unroll
        for (int ks = 0; ks < 32; ks += 16) {
            uint32_t ah[2][4], al[2][4];
#pragma unroll
            for (int mf = 0; mf < 2; mf++) {
                int m0 = wm * 32 + mf * 16;
                int kc = ks + tig * 2;
                ah[mf][0] = *reinterpret_cast<const uint32_t*>(&Ah[(m0 + gid)     * ASTRIDE + kc]);
                ah[mf][1] = *reinterpret_cast<const uint32_t*>(&Ah[(m0 + gid + 8) * ASTRIDE + kc]);
                ah[mf][2] = *reinterpret_cast<const uint32_t*>(&Ah[(m0 + gid)     * ASTRIDE + kc + 8]);
                ah[mf][3] = *reinterpret_cast<const uint32_t*>(&Ah[(m0 + gid + 8) * ASTRIDE + kc + 8]);
                al[mf][0] = *reinterpret_cast<const uint32_t*>(&Al[(m0 + gid)     * ASTRIDE + kc]);
                al[mf][1] = *reinterpret_cast<const uint32_t*>(&Al[(m0 + gid + 8) * ASTRIDE + kc]);
                al[mf][2] = *reinterpret_cast<const uint32_t*>(&Al[(m0 + gid)     * ASTRIDE + kc + 8]);
                al[mf][3] = *reinterpret_cast<const uint32_t*>(&Al[(m0 + gid + 8) * ASTRIDE + kc + 8]);
            }
            uint32_t bh[8][2], bl[8][2];
#pragma unroll
            for (int nf = 0; nf < 8; nf++) {
                int n0 = wn * 64 + nf * 8;
                int kc = ks + tig * 2;
                bh[nf][0] = *reinterpret_cast<const uint32_t*>(&Wh[(n0 + gid) * ASTRIDE + kc]);
                bh[nf][1] = *reinterpret_cast<const uint32_t*>(&Wh[(n0 + gid) * ASTRIDE + kc + 8]);
                bl[nf][0] = *reinterpret_cast<const uint32_t*>(&Wl[(n0 + gid) * ASTRIDE + kc]);
                bl[nf][1] = *reinterpret_cast<const uint32_t*>(&Wl[(n0 + gid) * ASTRIDE + kc + 8]);
            }
#pragma unroll
            for (int mf = 0; mf < 2; mf++)
#pragma unroll
                for (int nf = 0; nf < 8; nf++) {
                    mma16816(acc[mf][nf], ah[mf], bh[nf]);
                    mma16816(acc[mf][nf], ah[mf], bl[nf]);
                    mma16816(acc[mf][nf], al[mf], bh[nf]);
                }
        }
    }
}

// ---- K1 (HMMA): feat = relu(A @ W^T + b), fused allf assembly ---------------
__global__ __launch_bounds__(256) void k1_appear(
    const float* __restrict__ feat_in,
    const float* __restrict__ score, const float* __restrict__ box,
    const float* __restrict__ origin,
    const float* __restrict__ W, const float* __restrict__ b, int N)
{
    __shared__ __nv_bfloat16 Ah[128 * ASTRIDE], Al[128 * ASTRIDE];
    __shared__ __nv_bfloat16 Wh[128 * ASTRIDE], Wl[128 * ASTRIDE];
    const int tid  = threadIdx.x;
    const int w    = tid >> 5;
    const int lane = tid & 31;
    const int gid  = lane >> 2, tig = lane & 3;
    const int wm = w & 3, wn = w >> 2;
    const int mBase = blockIdx.x * 128;

    float acc[2][8][4];
    hmma_tile(feat_in + (size_t)mBase * 1024, 1024, N - mBase,
              W, 1024, 1024, Ah, Al, Wh, Wl, acc);

#pragma unroll
    for (int mf = 0; mf < 2; mf++)
#pragma unroll
        for (int nf = 0; nf < 8; nf++) {
            int m0 = mBase + wm * 32 + mf * 16 + gid;
            int n0 = wn * 64 + nf * 8 + tig * 2;
            if (m0 < N) {
                g_allf[(size_t)m0 * 224 + n0]     = fmaxf(acc[mf][nf][0] + b[n0],     0.f);
                g_allf[(size_t)m0 * 224 + n0 + 1] = fmaxf(acc[mf][nf][1] + b[n0 + 1], 0.f);
            }
            if (m0 + 8 < N) {
                g_allf[(size_t)(m0 + 8) * 224 + n0]     = fmaxf(acc[mf][nf][2] + b[n0],     0.f);
                g_allf[(size_t)(m0 + 8) * 224 + n0 + 1] = fmaxf(acc[mf][nf][3] + b[n0 + 1], 0.f);
            }
        }
    for (int idx = tid; idx < 128 * 96; idx += 256) {
        int r = idx / 96, jc = idx % 96;
        int m = mBase + r;
        if (m < N) {
            float v;
            if (jc < 32)      v = score [(size_t)m*32 + jc];
            else if (jc < 64) v = box   [(size_t)m*32 + jc - 32];
            else              v = origin[(size_t)m*32 + jc - 64];
            g_allf[(size_t)m*224 + 128 + jc] = v;
        }
    }
}

// ---- K2 (HMMA): dec = relu(allf @ feat_W^T + b), K=224 ----------------------
__global__ __launch_bounds__(256) void k2_dec(
    const float* __restrict__ W, const float* __restrict__ b, int N)
{
    __shared__ __nv_bfloat16 Ah[128 * ASTRIDE], Al[128 * ASTRIDE];
    __shared__ __nv_bfloat16 Wh[128 * ASTRIDE], Wl[128 * ASTRIDE];
    const int tid  = threadIdx.x;
    const int w    = tid >> 5;
    const int lane = tid & 31;
    const int gid  = lane >> 2, tig = lane & 3;
    const int wm = w & 3, wn = w >> 2;
    const int mBase = blockIdx.x * 128;

    float acc[2][8][4];
    hmma_tile(g_allf + (size_t)mBase * 224, 224, N - mBase,
              W, 224, 224, Ah, Al, Wh, Wl, acc);

#pragma unroll
    for (int mf = 0; mf < 2; mf++)
#pragma unroll
        for (int nf = 0; nf < 8; nf++) {
            int m0 = mBase + wm * 32 + mf * 16 + gid;
            int n0 = wn * 64 + nf * 8 + tig * 2;
            if (m0 < N) {
                g_dec[(size_t)m0 * 128 + n0]     = fmaxf(acc[mf][nf][0] + b[n0],     0.f);
                g_dec[(size_t)m0 * 128 + n0 + 1] = fmaxf(acc[mf][nf][1] + b[n0 + 1], 0.f);
            }
            if (m0 + 8 < N) {
                g_dec[(size_t)(m0 + 8) * 128 + n0]     = fmaxf(acc[mf][nf][2] + b[n0],     0.f);
                g_dec[(size_t)(m0 + 8) * 128 + n0 + 1] = fmaxf(acc[mf][nf][3] + b[n0 + 1], 0.f);
            }
        }
}

// ---- K3 (HMMA): Xp = dec @ Wih^T + bih, both dirs, K=128 --------------------
__global__ __launch_bounds__(256) void k3_xp(
    const float* __restrict__ Wih,   // C x 768 x 128
    const float* __restrict__ bih,   // C x 768
    int N)
{
    int c = blockIdx.z;
    int start = g_ucl[c];
    int len = g_ucl[c+1] - start;
    int mBase = blockIdx.y * 128;
    if (mBase >= len) return;
    int nBase = blockIdx.x * 128;

    __shared__ __nv_bfloat16 Ah[128 * ASTRIDE], Al[128 * ASTRIDE];
    __shared__ __nv_bfloat16 Wh[128 * ASTRIDE], Wl[128 * ASTRIDE];
    const int tid  = threadIdx.x;
    const int w    = tid >> 5;
    const int lane = tid & 31;
    const int gid  = lane >> 2, tig = lane & 3;
    const int wm = w & 3, wn = w >> 2;

    float acc[2][8][4];
    hmma_tile(g_dec + (size_t)(start + mBase) * 128, 128, len - mBase,
              Wih + ((size_t)c * 768 + nBase) * 128, 128, 128,
              Ah, Al, Wh, Wl, acc);

    const float* bb = bih + (size_t)c * 768;
    int d   = (nBase >= 384) ? 1 : 0;
    int nl0 = nBase - d * 384;
    float* dst = g_xp + (size_t)d * N * 384 + (size_t)start * 384;
#pragma unroll
    for (int mf = 0; mf < 2; mf++)
#pragma unroll
        for (int nf = 0; nf < 8; nf++) {
            int ml = mBase + wm * 32 + mf * 16 + gid;
            int n0 = wn * 64 + nf * 8 + tig * 2;
            int ng = nBase + n0;
            if (ml < len) {
                dst[(size_t)ml * 384 + nl0 + n0]     = acc[mf][nf][0] + bb[ng];
                dst[(size_t)ml * 384 + nl0 + n0 + 1] = acc[mf][nf][1] + bb[ng + 1];
            }
            if (ml + 8 < len) {
                dst[(size_t)(ml + 8) * 384 + nl0 + n0]     = acc[mf][nf][2] + bb[ng];
                dst[(size_t)(ml + 8) * 384 + nl0 + n0 + 1] = acc[mf][nf][3] + bb[ng + 1];
            }
        }
}

// ---- packed f32x2 FMA ------------------------------------------------------
__device__ __forceinline__ void fma2(unsigned long long& d,
                                     unsigned long long a,
                                     unsigned long long b) {
    asm("fma.rn.f32x2 %0, %1, %2, %0;" : "+l"(d) : "l"(a), "l"(b));
}

// ---- K4: sequential GRU, one block per (class, dir), Whh in registers ------
__global__ __launch_bounds__(384, 1) void k4_gru(
    const float* __restrict__ Whh, const float* __restrict__ bhh, int N)
{
    int bid = blockIdx.x;
    int c = (CC - 1) - (bid >> 1);
    int d = bid & 1;
    int start = g_ucl[c];
    int len = g_ucl[c+1] - start;
    int g = threadIdx.x;

    __shared__ __align__(16) float h_sm[128];
    __shared__ float pre[256];
    __shared__ float gh3[128];
    __shared__ float x3s[128];

    unsigned long long w2[64];
    {
        const ulonglong2* wp = reinterpret_cast<const ulonglong2*>(
            Whh + ((size_t)(c*2 + d) * 384 + g) * 128);
#pragma unroll
        for (int k = 0; k < 32; k++) {
            ulonglong2 v = wp[k];
            w2[2*k]   = v.x;
            w2[2*k+1] = v.y;
        }
    }
    float bg = bhh[(size_t)(c*2 + d) * 384 + g];
    if (g < 128) h_sm[g] = 0.f;
    __syncthreads();

    const float* Xp = g_xp  + (size_t)d * N * 384 + (size_t)start * 384;
    float* Hout     = g_hid + (size_t)d * N * 128 + (size_t)start * 128;

    int j  = (d == 0) ? 0 : len - 1;
    int dj = (d == 0) ? 1 : -1;
    float xg = (len > 0) ? Xp[(size_t)j * 384 + g] : 0.f;

    for (int step = 0; step < len; step++) {
        int jn = j + dj;
        float xn = 0.f;
        if (step + 1 < len) xn = Xp[(size_t)jn * 384 + g];

        unsigned long long a0 = 0ULL, a1 = 0ULL, a2 = 0ULL, a3 = 0ULL;
        const ulonglong2* h2 = reinterpret_cast<const ulonglong2*>(h_sm);
#pragma unroll
        for (int k = 0; k < 32; k += 2) {
            ulonglong2 hv0 = h2[k];
            ulonglong2 hv1 = h2[k+1];
            fma2(a0, w2[2*k],   hv0.x);
            fma2(a1, w2[2*k+1], hv0.y);
            fma2(a2, w2[2*k+2], hv1.x);
            fma2(a3, w2[2*k+3], hv1.y);
        }
        float2 f0 = *reinterpret_cast<float2*>(&a0);
        float2 f1 = *reinterpret_cast<float2*>(&a1);
        float2 f2 = *reinterpret_cast<float2*>(&a2);
        float2 f3 = *reinterpret_cast<float2*>(&a3);
        float gh = ((f0.x + f0.y) + (f1.x + f1.y))
                 + ((f2.x + f2.y) + (f3.x + f3.y)) + bg;

        if (g < 256) pre[g] = xg + gh;
        else { gh3[g - 256] = gh; x3s[g - 256] = xg; }
        __syncthreads();
        if (g < 128) {
            float r  = __fdividef(1.f, 1.f + __expf(-pre[g]));
            float z  = __fdividef(1.f, 1.f + __expf(-pre[128 + g]));
            float u  = x3s[g] + r * gh3[g];
            u = fminf(fmaxf(u, -15.f), 15.f);
            float e  = __expf(-2.f * u);
            float nn = __fdividef(1.f - e, 1.f + e);
            float hp = h_sm[g];
            float h2v = (1.f - z) * nn + z * hp;
            h_sm[g] = h2v;
            Hout[(size_t)j * 128 + g] = h2v;
        }
        __syncthreads();
        xg = xn;
        j = jn;
    }
}

// ---- K5: out = sigmoid([hf|hb] . out_W + b) --------------------------------
__global__ __launch_bounds__(256) void k5_out(
    const float* __restrict__ outW, const float* __restrict__ outb,
    float* __restrict__ out, int N)
{
    int t = blockIdx.x * blockDim.x + threadIdx.x;
    int row = t >> 5, lane = t & 31;
    if (row >= N) return;
    const float* hf = g_hid + (size_t)row * 128;
    const float* hb = g_hid + (size_t)N * 128 + (size_t)row * 128;
    float s = 0.f;
#pragma unroll
    for (int k = lane; k < 128; k += 32)
        s += outW[k] * hf[k] + outW[128 + k] * hb[k];
#pragma unroll
    for (int o = 16; o > 0; o >>= 1)
        s += __shfl_down_sync(0xffffffffu, s, o);
    if (lane == 0)
        out[row] = __fdividef(1.f, 1.f + __expf(-(s + outb[0])));
}

extern "C" void kernel_launch(void* const* d_in, const int* in_sizes, int n_in,
                              void* d_out, int out_size)
{
    const float* acb_feat  = (const float*)d_in[3];
    const float* acb_score = (const float*)d_in[4];
    const float* acb_box   = (const float*)d_in[5];
    const float* acb_orig  = (const float*)d_in[6];
    const void*  ucl_raw   = d_in[8];
    const float* appear_W  = (const float*)d_in[9];
    const float* appear_b  = (const float*)d_in[10];
    const float* feat_W    = (const float*)d_in[11];
    const float* feat_b    = (const float*)d_in[12];
    const float* gru_Wih   = (const float*)d_in[13];
    const float* gru_Whh   = (const float*)d_in[14];
    const float* gru_bih   = (const float*)d_in[15];
    const float* gru_bhh   = (const float*)d_in[16];
    const float* out_W     = (const float*)d_in[17];
    const float* out_b     = (const float*)d_in[18];

    int N = in_sizes[3] / 1024;
    if (N > MAXN) N = MAXN;
    int Mtiles = (N + 127) / 128;

    k0_ucl<<<1, 32>>>(ucl_raw);
    k1_appear<<<Mtiles, 256>>>(acb_feat, acb_score, acb_box, acb_orig,
                               appear_W, appear_b, N);
    k2_dec<<<Mtiles, 256>>>(feat_W, feat_b, N);
    dim3 g3(6, 4, CC);
    k3_xp<<<g3, 256>>>(gru_Wih, gru_bih, N);
    k4_gru<<<2 * CC, 384>>>(gru_Whh, gru_bhh, N);
    k5_out<<<(N * 32 + 255) / 256, 256>>>(out_W, out_b, (float*)d_out, N);
}

// round 8
// speedup vs baseline: 1.5828x; 1.0719x over previous
#include <cuda_runtime.h>
#include <cuda_bf16.h>
#include <math.h>
#include <cstdint>

#define HH 128
#define CC 80
#define MAXN 24576
#define ASTRIDE 40   // bf16 elems per smem row (bank-conflict-free for 16816 frag reads)

// ---------------- scratch ----------------------------------------------------
__device__ __align__(256) float g_allf[(size_t)MAXN * 224];
__device__ __align__(256) float g_dec [(size_t)MAXN * 128];
__device__ __align__(256) float g_xp  [(size_t)2 * MAXN * 384];
__device__ __align__(256) float g_hid [(size_t)2 * MAXN * 128];
__device__ int g_ucl[CC + 1];

// ---- K0: normalize unique_class_len (int32 or int64 input), parallel -------
__global__ void k0_ucl(const void* __restrict__ ucl_raw) {
    __shared__ int is64;
    const int* p32 = (const int*)ucl_raw;
    if (threadIdx.x == 0) is64 = (p32[1] == 0);   // int64 LE small -> high word 0
    __syncthreads();
    int i = threadIdx.x;
    if (i <= CC) {
        g_ucl[i] = is64 ? (int)((const long long*)ucl_raw)[i] : p32[i];
    }
}

// ---- bf16 pack helpers -------------------------------------------------------
__device__ __forceinline__ uint32_t pack_hi(float x, float y) {
    __nv_bfloat16 hx = __float2bfloat16(x), hy = __float2bfloat16(y);
    return ((uint32_t)__bfloat16_as_ushort(hy) << 16) | __bfloat16_as_ushort(hx);
}
__device__ __forceinline__ uint32_t pack_lo(float x, float y) {
    __nv_bfloat16 hx = __float2bfloat16(x), hy = __float2bfloat16(y);
    __nv_bfloat16 lx = __float2bfloat16(x - __bfloat162float(hx));
    __nv_bfloat16 ly = __float2bfloat16(y - __bfloat162float(hy));
    return ((uint32_t)__bfloat16_as_ushort(ly) << 16) | __bfloat16_as_ushort(lx);
}

// ---- m16n8k16 bf16 MMA (arch-neutral PTX; tensor pipe) ----------------------
__device__ __forceinline__ void mma16816(float c[4], const uint32_t a[4], const uint32_t b[2]) {
    asm volatile(
        "mma.sync.aligned.m16n8k16.row.col.f32.bf16.bf16.f32 "
        "{%0,%1,%2,%3}, {%4,%5,%6,%7}, {%8,%9}, {%0,%1,%2,%3};"
        : "+f"(c[0]), "+f"(c[1]), "+f"(c[2]), "+f"(c[3])
        : "r"(a[0]), "r"(a[1]), "r"(a[2]), "r"(a[3]), "r"(b[0]), "r"(b[1]));
}

// ---- HMMA 128x128 tile core with register-prefetch pipeline -----------------
// Next chunk's LDGs issue before the MMA section -> DRAM/L2 latency hidden.
__device__ __forceinline__ void hmma_tile(
    const float* __restrict__ At, int lda, int mValid,
    const float* __restrict__ Bt, int ldb, int KTOT,
    __nv_bfloat16* Ah, __nv_bfloat16* Al,
    __nv_bfloat16* Wh, __nv_bfloat16* Wl,
    float acc[2][8][4])
{
    const int tid  = threadIdx.x;
    const int w    = tid >> 5;
    const int lane = tid & 31;
    const int gid  = lane >> 2;
    const int tig  = lane & 3;
    const int wm   = w & 3;
    const int wn   = w >> 2;
    const int rr   = tid >> 3;          // 0..31 base row (4 passes of +32? no: idx mapping below)

#pragma unroll
    for (int i = 0; i < 2; i++)
#pragma unroll
        for (int j = 0; j < 8; j++)
#pragma unroll
            for (int q = 0; q < 4; q++) acc[i][j][q] = 0.f;

    float4 pA[4], pB[4];
    // prefetch chunk 0
#pragma unroll
    for (int it = 0; it < 4; it++) {
        int idx = tid + it * 256;
        int r  = idx >> 3;
        int c4 = (idx & 7) * 4;
        pA[it] = (r < mValid) ? *reinterpret_cast<const float4*>(At + (size_t)r * lda + c4)
                              : make_float4(0.f, 0.f, 0.f, 0.f);
        pB[it] = *reinterpret_cast<const float4*>(Bt + (size_t)r * ldb + c4);
    }

    for (int k0 = 0; k0 < KTOT; k0 += 32) {
        // store prefetched chunk into smem (convert to bf16 hi/lo)
#pragma unroll
        for (int it = 0; it < 4; it++) {
            int idx = tid + it * 256;
            int r  = idx >> 3;
            int c4 = (idx & 7) * 4;
            int o = r * ASTRIDE + c4;
            float4 v = pA[it];
            *reinterpret_cast<uint32_t*>(&Ah[o])     = pack_hi(v.x, v.y);
            *reinterpret_cast<uint32_t*>(&Ah[o + 2]) = pack_hi(v.z, v.w);
            *reinterpret_cast<uint32_t*>(&Al[o])     = pack_lo(v.x, v.y);
            *reinterpret_cast<uint32_t*>(&Al[o + 2]) = pack_lo(v.z, v.w);
            v = pB[it];
            *reinterpret_cast<uint32_t*>(&Wh[o])     = pack_hi(v.x, v.y);
            *reinterpret_cast<uint32_t*>(&Wh[o + 2]) = pack_hi(v.z, v.w);
            *reinterpret_cast<uint32_t*>(&Wl[o])     = pack_lo(v.x, v.y);
            *reinterpret_cast<uint32_t*>(&Wl[o + 2]) = pack_lo(v.z, v.w);
        }
        __syncthreads();

        // prefetch next chunk (overlaps with MMA below)
        if (k0 + 32 < KTOT) {
#pragma unroll
            for (int it = 0; it < 4; it++) {
                int idx = tid + it * 256;
                int r  = idx >> 3;
                int c4 = (idx & 7) * 4;
                pA[it] = (r < mValid) ? *reinterpret_cast<const float4*>(At + (size_t)r * lda + k0 + 32 + c4)
                                      : make_float4(0.f, 0.f, 0.f, 0.f);
                pB[it] = *reinterpret_cast<const float4*>(Bt + (size_t)r * ldb + k0 + 32 + c4);
            }
        }

#pragma unroll
        for (int ks = 0; ks < 32; ks += 16) {
            uint32_t ah[2][4], al[2][4];
#pragma unroll
            for (int mf = 0; mf < 2; mf++) {
                int m0 = wm * 32 + mf * 16;
                int kc = ks + tig * 2;
                ah[mf][0] = *reinterpret_cast<const uint32_t*>(&Ah[(m0 + gid)     * ASTRIDE + kc]);
                ah[mf][1] = *reinterpret_cast<const uint32_t*>(&Ah[(m0 + gid + 8) * ASTRIDE + kc]);
                ah[mf][2] = *reinterpret_cast<const uint32_t*>(&Ah[(m0 + gid)     * ASTRIDE + kc + 8]);
                ah[mf][3] = *reinterpret_cast<const uint32_t*>(&Ah[(m0 + gid + 8) * ASTRIDE + kc + 8]);
                al[mf][0] = *reinterpret_cast<const uint32_t*>(&Al[(m0 + gid)     * ASTRIDE + kc]);
                al[mf][1] = *reinterpret_cast<const uint32_t*>(&Al[(m0 + gid + 8) * ASTRIDE + kc]);
                al[mf][2] = *reinterpret_cast<const uint32_t*>(&Al[(m0 + gid)     * ASTRIDE + kc + 8]);
                al[mf][3] = *reinterpret_cast<const uint32_t*>(&Al[(m0 + gid + 8) * ASTRIDE + kc + 8]);
            }
            uint32_t bh[8][2], bl[8][2];
#pragma unroll
            for (int nf = 0; nf < 8; nf++) {
                int n0 = wn * 64 + nf * 8;
                int kc = ks + tig * 2;
                bh[nf][0] = *reinterpret_cast<const uint32_t*>(&Wh[(n0 + gid) * ASTRIDE + kc]);
                bh[nf][1] = *reinterpret_cast<const uint32_t*>(&Wh[(n0 + gid) * ASTRIDE + kc + 8]);
                bl[nf][0] = *reinterpret_cast<const uint32_t*>(&Wl[(n0 + gid) * ASTRIDE + kc]);
                bl[nf][1] = *reinterpret_cast<const uint32_t*>(&Wl[(n0 + gid) * ASTRIDE + kc + 8]);
            }
#pragma unroll
            for (int mf = 0; mf < 2; mf++)
#pragma unroll
                for (int nf = 0; nf < 8; nf++) {
                    mma16816(acc[mf][nf], ah[mf], bh[nf]);
                    mma16816(acc[mf][nf], ah[mf], bl[nf]);
                    mma16816(acc[mf][nf], al[mf], bh[nf]);
                }
        }
        __syncthreads();
    }
}

// ---- K1 (HMMA): feat = relu(A @ W^T + b), fused allf assembly ---------------
__global__ __launch_bounds__(256) void k1_appear(
    const float* __restrict__ feat_in,
    const float* __restrict__ score, const float* __restrict__ box,
    const float* __restrict__ origin,
    const float* __restrict__ W, const float* __restrict__ b, int N)
{
    __shared__ __nv_bfloat16 Ah[128 * ASTRIDE], Al[128 * ASTRIDE];
    __shared__ __nv_bfloat16 Wh[128 * ASTRIDE], Wl[128 * ASTRIDE];
    const int tid  = threadIdx.x;
    const int w    = tid >> 5;
    const int lane = tid & 31;
    const int gid  = lane >> 2, tig = lane & 3;
    const int wm = w & 3, wn = w >> 2;
    const int mBase = blockIdx.x * 128;

    float acc[2][8][4];
    hmma_tile(feat_in + (size_t)mBase * 1024, 1024, N - mBase,
              W, 1024, 1024, Ah, Al, Wh, Wl, acc);

#pragma unroll
    for (int mf = 0; mf < 2; mf++)
#pragma unroll
        for (int nf = 0; nf < 8; nf++) {
            int m0 = mBase + wm * 32 + mf * 16 + gid;
            int n0 = wn * 64 + nf * 8 + tig * 2;
            if (m0 < N) {
                g_allf[(size_t)m0 * 224 + n0]     = fmaxf(acc[mf][nf][0] + b[n0],     0.f);
                g_allf[(size_t)m0 * 224 + n0 + 1] = fmaxf(acc[mf][nf][1] + b[n0 + 1], 0.f);
            }
            if (m0 + 8 < N) {
                g_allf[(size_t)(m0 + 8) * 224 + n0]     = fmaxf(acc[mf][nf][2] + b[n0],     0.f);
                g_allf[(size_t)(m0 + 8) * 224 + n0 + 1] = fmaxf(acc[mf][nf][3] + b[n0 + 1], 0.f);
            }
        }
    for (int idx = tid; idx < 128 * 96; idx += 256) {
        int r = idx / 96, jc = idx % 96;
        int m = mBase + r;
        if (m < N) {
            float v;
            if (jc < 32)      v = score [(size_t)m*32 + jc];
            else if (jc < 64) v = box   [(size_t)m*32 + jc - 32];
            else              v = origin[(size_t)m*32 + jc - 64];
            g_allf[(size_t)m*224 + 128 + jc] = v;
        }
    }
}

// ---- K2 (HMMA): dec = relu(allf @ feat_W^T + b), K=224 ----------------------
__global__ __launch_bounds__(256) void k2_dec(
    const float* __restrict__ W, const float* __restrict__ b, int N)
{
    __shared__ __nv_bfloat16 Ah[128 * ASTRIDE], Al[128 * ASTRIDE];
    __shared__ __nv_bfloat16 Wh[128 * ASTRIDE], Wl[128 * ASTRIDE];
    const int tid  = threadIdx.x;
    const int w    = tid >> 5;
    const int lane = tid & 31;
    const int gid  = lane >> 2, tig = lane & 3;
    const int wm = w & 3, wn = w >> 2;
    const int mBase = blockIdx.x * 128;

    float acc[2][8][4];
    hmma_tile(g_allf + (size_t)mBase * 224, 224, N - mBase,
              W, 224, 224, Ah, Al, Wh, Wl, acc);

#pragma unroll
    for (int mf = 0; mf < 2; mf++)
#pragma unroll
        for (int nf = 0; nf < 8; nf++) {
            int m0 = mBase + wm * 32 + mf * 16 + gid;
            int n0 = wn * 64 + nf * 8 + tig * 2;
            if (m0 < N) {
                g_dec[(size_t)m0 * 128 + n0]     = fmaxf(acc[mf][nf][0] + b[n0],     0.f);
                g_dec[(size_t)m0 * 128 + n0 + 1] = fmaxf(acc[mf][nf][1] + b[n0 + 1], 0.f);
            }
            if (m0 + 8 < N) {
                g_dec[(size_t)(m0 + 8) * 128 + n0]     = fmaxf(acc[mf][nf][2] + b[n0],     0.f);
                g_dec[(size_t)(m0 + 8) * 128 + n0 + 1] = fmaxf(acc[mf][nf][3] + b[n0 + 1], 0.f);
            }
        }
}

// ---- K3 (HMMA): Xp = dec @ Wih^T + bih, both dirs, K=128 --------------------
__global__ __launch_bounds__(256) void k3_xp(
    const float* __restrict__ Wih,   // C x 768 x 128
    const float* __restrict__ bih,   // C x 768
    int N)
{
    int c = blockIdx.z;
    int start = g_ucl[c];
    int len = g_ucl[c+1] - start;
    int mBase = blockIdx.y * 128;
    if (mBase >= len) return;
    int nBase = blockIdx.x * 128;

    __shared__ __nv_bfloat16 Ah[128 * ASTRIDE], Al[128 * ASTRIDE];
    __shared__ __nv_bfloat16 Wh[128 * ASTRIDE], Wl[128 * ASTRIDE];
    const int tid  = threadIdx.x;
    const int w    = tid >> 5;
    const int lane = tid & 31;
    const int gid  = lane >> 2, tig = lane & 3;
    const int wm = w & 3, wn = w >> 2;

    float acc[2][8][4];
    hmma_tile(g_dec + (size_t)(start + mBase) * 128, 128, len - mBase,
              Wih + ((size_t)c * 768 + nBase) * 128, 128, 128,
              Ah, Al, Wh, Wl, acc);

    const float* bb = bih + (size_t)c * 768;
    int d   = (nBase >= 384) ? 1 : 0;
    int nl0 = nBase - d * 384;
    float* dst = g_xp + (size_t)d * N * 384 + (size_t)start * 384;
#pragma unroll
    for (int mf = 0; mf < 2; mf++)
#pragma unroll
        for (int nf = 0; nf < 8; nf++) {
            int ml = mBase + wm * 32 + mf * 16 + gid;
            int n0 = wn * 64 + nf * 8 + tig * 2;
            int ng = nBase + n0;
            if (ml < len) {
                dst[(size_t)ml * 384 + nl0 + n0]     = acc[mf][nf][0] + bb[ng];
                dst[(size_t)ml * 384 + nl0 + n0 + 1] = acc[mf][nf][1] + bb[ng + 1];
            }
            if (ml + 8 < len) {
                dst[(size_t)(ml + 8) * 384 + nl0 + n0]     = acc[mf][nf][2] + bb[ng];
                dst[(size_t)(ml + 8) * 384 + nl0 + n0 + 1] = acc[mf][nf][3] + bb[ng + 1];
            }
        }
}

// ---- packed f32x2 FMA + fast tanh -------------------------------------------
__device__ __forceinline__ void fma2(unsigned long long& d,
                                     unsigned long long a,
                                     unsigned long long b) {
    asm("fma.rn.f32x2 %0, %1, %2, %0;" : "+l"(d) : "l"(a), "l"(b));
}
__device__ __forceinline__ float fast_tanh(float x) {
    float y;
    asm("tanh.approx.f32 %0, %1;" : "=f"(y) : "f"(x));
    return y;
}

// ---- K4: sequential GRU, one block per (class, dir), Whh in registers ------
__global__ __launch_bounds__(384, 1) void k4_gru(
    const float* __restrict__ Whh, const float* __restrict__ bhh, int N)
{
    int bid = blockIdx.x;
    int c = (CC - 1) - (bid >> 1);   // longest classes first
    int d = bid & 1;
    int start = g_ucl[c];
    int len = g_ucl[c+1] - start;
    int g = threadIdx.x;

    __shared__ __align__(16) float h_sm[128];
    __shared__ float pre[256];
    __shared__ float gh3[128];
    __shared__ float x3s[128];

    unsigned long long w2[64];
    {
        const ulonglong2* wp = reinterpret_cast<const ulonglong2*>(
            Whh + ((size_t)(c*2 + d) * 384 + g) * 128);
#pragma unroll
        for (int k = 0; k < 32; k++) {
            ulonglong2 v = wp[k];
            w2[2*k]   = v.x;
            w2[2*k+1] = v.y;
        }
    }
    float bg = bhh[(size_t)(c*2 + d) * 384 + g];
    if (g < 128) h_sm[g] = 0.f;
    __syncthreads();

    const float* Xp = g_xp  + (size_t)d * N * 384 + (size_t)start * 384;
    float* Hout     = g_hid + (size_t)d * N * 128 + (size_t)start * 128;

    int j  = (d == 0) ? 0 : len - 1;
    int dj = (d == 0) ? 1 : -1;
    float xg = (len > 0) ? Xp[(size_t)j * 384 + g] : 0.f;

    for (int step = 0; step < len; step++) {
        int jn = j + dj;
        float xn = 0.f;
        if (step + 1 < len) xn = Xp[(size_t)jn * 384 + g];

        unsigned long long a0 = 0ULL, a1 = 0ULL, a2 = 0ULL, a3 = 0ULL;
        const ulonglong2* h2 = reinterpret_cast<const ulonglong2*>(h_sm);
#pragma unroll
        for (int k = 0; k < 32; k += 2) {
            ulonglong2 hv0 = h2[k];
            ulonglong2 hv1 = h2[k+1];
            fma2(a0, w2[2*k],   hv0.x);
            fma2(a1, w2[2*k+1], hv0.y);
            fma2(a2, w2[2*k+2], hv1.x);
            fma2(a3, w2[2*k+3], hv1.y);
        }
        float2 f0 = *reinterpret_cast<float2*>(&a0);
        float2 f1 = *reinterpret_cast<float2*>(&a1);
        float2 f2 = *reinterpret_cast<float2*>(&a2);
        float2 f3 = *reinterpret_cast<float2*>(&a3);
        float gh = ((f0.x + f0.y) + (f1.x + f1.y))
                 + ((f2.x + f2.y) + (f3.x + f3.y)) + bg;

        if (g < 256) pre[g] = xg + gh;
        else { gh3[g - 256] = gh; x3s[g - 256] = xg; }
        __syncthreads();
        if (g < 128) {
            float r  = fmaf(fast_tanh(pre[g]       * 0.5f), 0.5f, 0.5f);
            float z  = fmaf(fast_tanh(pre[128 + g] * 0.5f), 0.5f, 0.5f);
            float u  = x3s[g] + r * gh3[g];
            float nn = fast_tanh(u);
            float hp = h_sm[g];
            float h2v = fmaf(z, hp - nn, nn);
            h_sm[g] = h2v;
            Hout[(size_t)j * 128 + g] = h2v;
        }
        __syncthreads();
        xg = xn;
        j = jn;
    }
}

// ---- K5: out = sigmoid([hf|hb] . out_W + b) --------------------------------
__global__ __launch_bounds__(256) void k5_out(
    const float* __restrict__ outW, const float* __restrict__ outb,
    float* __restrict__ out, int N)
{
    int t = blockIdx.x * blockDim.x + threadIdx.x;
    int row = t >> 5, lane = t & 31;
    if (row >= N) return;
    const float* hf = g_hid + (size_t)row * 128;
    const float* hb = g_hid + (size_t)N * 128 + (size_t)row * 128;
    float s = 0.f;
#pragma unroll
    for (int k = lane; k < 128; k += 32)
        s += outW[k] * hf[k] + outW[128 + k] * hb[k];
#pragma unroll
    for (int o = 16; o > 0; o >>= 1)
        s += __shfl_down_sync(0xffffffffu, s, o);
    if (lane == 0)
        out[row] = __fdividef(1.f, 1.f + __expf(-(s + outb[0])));
}

extern "C" void kernel_launch(void* const* d_in, const int* in_sizes, int n_in,
                              void* d_out, int out_size)
{
    const float* acb_feat  = (const float*)d_in[3];
    const float* acb_score = (const float*)d_in[4];
    const float* acb_box   = (const float*)d_in[5];
    const float* acb_orig  = (const float*)d_in[6];
    const void*  ucl_raw   = d_in[8];
    const float* appear_W  = (const float*)d_in[9];
    const float* appear_b  = (const float*)d_in[10];
    const float* feat_W    = (const float*)d_in[11];
    const float* feat_b    = (const float*)d_in[12];
    const float* gru_Wih   = (const float*)d_in[13];
    const float* gru_Whh   = (const float*)d_in[14];
    const float* gru_bih   = (const float*)d_in[15];
    const float* gru_bhh   = (const float*)d_in[16];
    const float* out_W     = (const float*)d_in[17];
    const float* out_b     = (const float*)d_in[18];

    int N = in_sizes[3] / 1024;
    if (N > MAXN) N = MAXN;
    int Mtiles = (N + 127) / 128;

    k0_ucl<<<1, 96>>>(ucl_raw);
    k1_appear<<<Mtiles, 256>>>(acb_feat, acb_score, acb_box, acb_orig,
                               appear_W, appear_b, N);
    k2_dec<<<Mtiles, 256>>>(feat_W, feat_b, N);
    dim3 g3(6, 4, CC);
    k3_xp<<<g3, 256>>>(gru_Wih, gru_bih, N);
    k4_gru<<<2 * CC, 384>>>(gru_Whh, gru_bhh, N);
    k5_out<<<(N * 32 + 255) / 256, 256>>>(out_W, out_b, (float*)d_out, N);
}

// round 9
// speedup vs baseline: 1.6807x; 1.0618x over previous
#include <cuda_runtime.h>
#include <cuda_bf16.h>
#include <math.h>
#include <cstdint>

#define HH 128
#define CC 80
#define MAXN 24576
#define ASTRIDE 40   // bf16 elems per smem row (bank-conflict-free for 16816 frag reads)

// ---------------- scratch ----------------------------------------------------
__device__ __align__(256) __nv_bfloat16 g_allf_h[(size_t)MAXN * 224];
__device__ __align__(256) __nv_bfloat16 g_allf_l[(size_t)MAXN * 224];
__device__ __align__(256) __nv_bfloat16 g_dec_h [(size_t)MAXN * 128];
__device__ __align__(256) __nv_bfloat16 g_dec_l [(size_t)MAXN * 128];
__device__ __align__(256) __nv_bfloat16 g_wih_h [(size_t)CC * 768 * 128];
__device__ __align__(256) __nv_bfloat16 g_wih_l [(size_t)CC * 768 * 128];
__device__ __align__(256) __nv_bfloat16 g_apw_h [128 * 1024];
__device__ __align__(256) __nv_bfloat16 g_apw_l [128 * 1024];
__device__ __align__(256) __nv_bfloat16 g_fw_h  [128 * 224];
__device__ __align__(256) __nv_bfloat16 g_fw_l  [128 * 224];
__device__ __align__(256) float g_xp  [(size_t)2 * MAXN * 384];
__device__ __align__(256) float g_hid [(size_t)2 * MAXN * 128];
__device__ int g_ucl[CC + 1];

// ---- K0: normalize unique_class_len (int32 or int64 input), parallel -------
__global__ void k0_ucl(const void* __restrict__ ucl_raw) {
    __shared__ int is64;
    const int* p32 = (const int*)ucl_raw;
    if (threadIdx.x == 0) is64 = (p32[1] == 0);
    __syncthreads();
    int i = threadIdx.x;
    if (i <= CC) {
        g_ucl[i] = is64 ? (int)((const long long*)ucl_raw)[i] : p32[i];
    }
}

// ---- fast packed bf16 conversion helpers ------------------------------------
// hi: x -> low half, y -> high half (cvt d,a,b: a->upper, b->lower)
__device__ __forceinline__ uint32_t pk_hi(float x, float y) {
    uint32_t r;
    asm("cvt.rn.bf16x2.f32 %0, %1, %2;" : "=r"(r) : "f"(y), "f"(x));
    return r;
}
__device__ __forceinline__ uint32_t pk_lo(float x, float y, uint32_t ph) {
    float hx = __uint_as_float(ph << 16);
    float hy = __uint_as_float(ph & 0xFFFF0000u);
    uint32_t r;
    float rx = x - hx, ry = y - hy;
    asm("cvt.rn.bf16x2.f32 %0, %1, %2;" : "=r"(r) : "f"(ry), "f"(rx));
    return r;
}

// ---- KW: generic fp32 -> bf16 hi/lo stream converter ------------------------
__global__ __launch_bounds__(256) void kconv(
    const float* __restrict__ src,
    __nv_bfloat16* __restrict__ dh, __nv_bfloat16* __restrict__ dl, int n4)
{
    int i = blockIdx.x * blockDim.x + threadIdx.x;
    if (i >= n4) return;
    float4 v = reinterpret_cast<const float4*>(src)[i];
    uint32_t h0 = pk_hi(v.x, v.y), h1 = pk_hi(v.z, v.w);
    uint32_t l0 = pk_lo(v.x, v.y, h0), l1 = pk_lo(v.z, v.w, h1);
    reinterpret_cast<uint2*>(dh)[i] = make_uint2(h0, h1);
    reinterpret_cast<uint2*>(dl)[i] = make_uint2(l0, l1);
}

// ---- m16n8k16 bf16 MMA -------------------------------------------------------
__device__ __forceinline__ void mma16816(float c[4], const uint32_t a[4], const uint32_t b[2]) {
    asm volatile(
        "mma.sync.aligned.m16n8k16.row.col.f32.bf16.bf16.f32 "
        "{%0,%1,%2,%3}, {%4,%5,%6,%7}, {%8,%9}, {%0,%1,%2,%3};"
        : "+f"(c[0]), "+f"(c[1]), "+f"(c[2]), "+f"(c[3])
        : "r"(a[0]), "r"(a[1]), "r"(a[2]), "r"(a[3]), "r"(b[0]), "r"(b[1]));
}

// ---- shared MMA section over staged smem tiles ------------------------------
__device__ __forceinline__ void mma_section(
    const __nv_bfloat16* Ah, const __nv_bfloat16* Al,
    const __nv_bfloat16* Wh, const __nv_bfloat16* Wl,
    int wm, int wn, int gid, int tig, float acc[2][8][4])
{
#pragma unroll
    for (int ks = 0; ks < 32; ks += 16) {
        uint32_t ah[2][4], al[2][4];
#pragma unroll
        for (int mf = 0; mf < 2; mf++) {
            int m0 = wm * 32 + mf * 16;
            int kc = ks + tig * 2;
            ah[mf][0] = *reinterpret_cast<const uint32_t*>(&Ah[(m0 + gid)     * ASTRIDE + kc]);
            ah[mf][1] = *reinterpret_cast<const uint32_t*>(&Ah[(m0 + gid + 8) * ASTRIDE + kc]);
            ah[mf][2] = *reinterpret_cast<const uint32_t*>(&Ah[(m0 + gid)     * ASTRIDE + kc + 8]);
            ah[mf][3] = *reinterpret_cast<const uint32_t*>(&Ah[(m0 + gid + 8) * ASTRIDE + kc + 8]);
            al[mf][0] = *reinterpret_cast<const uint32_t*>(&Al[(m0 + gid)     * ASTRIDE + kc]);
            al[mf][1] = *reinterpret_cast<const uint32_t*>(&Al[(m0 + gid + 8) * ASTRIDE + kc]);
            al[mf][2] = *reinterpret_cast<const uint32_t*>(&Al[(m0 + gid)     * ASTRIDE + kc + 8]);
            al[mf][3] = *reinterpret_cast<const uint32_t*>(&Al[(m0 + gid + 8) * ASTRIDE + kc + 8]);
        }
        uint32_t bh[8][2], bl[8][2];
#pragma unroll
        for (int nf = 0; nf < 8; nf++) {
            int n0 = wn * 64 + nf * 8;
            int kc = ks + tig * 2;
            bh[nf][0] = *reinterpret_cast<const uint32_t*>(&Wh[(n0 + gid) * ASTRIDE + kc]);
            bh[nf][1] = *reinterpret_cast<const uint32_t*>(&Wh[(n0 + gid) * ASTRIDE + kc + 8]);
            bl[nf][0] = *reinterpret_cast<const uint32_t*>(&Wl[(n0 + gid) * ASTRIDE + kc]);
            bl[nf][1] = *reinterpret_cast<const uint32_t*>(&Wl[(n0 + gid) * ASTRIDE + kc + 8]);
        }
#pragma unroll
        for (int mf = 0; mf < 2; mf++)
#pragma unroll
            for (int nf = 0; nf < 8; nf++) {
                mma16816(acc[mf][nf], ah[mf], bh[nf]);
                mma16816(acc[mf][nf], ah[mf], bl[nf]);
                mma16816(acc[mf][nf], al[mf], bh[nf]);
            }
    }
}

// ---- tile core: A fp32 (convert on stage), B pre-converted bf16 hi/lo -------
__device__ __forceinline__ void hmma_tile_mixed(
    const float* __restrict__ At, int lda, int mValid,
    const __nv_bfloat16* __restrict__ Bh_g, const __nv_bfloat16* __restrict__ Bl_g, int ldb,
    int KTOT,
    __nv_bfloat16* Ah, __nv_bfloat16* Al,
    __nv_bfloat16* Wh, __nv_bfloat16* Wl,
    float acc[2][8][4])
{
    const int tid  = threadIdx.x;
    const int w    = tid >> 5;
    const int lane = tid & 31;
    const int gid  = lane >> 2, tig = lane & 3;
    const int wm = w & 3, wn = w >> 2;

#pragma unroll
    for (int i = 0; i < 2; i++)
#pragma unroll
        for (int j = 0; j < 8; j++)
#pragma unroll
            for (int q = 0; q < 4; q++) acc[i][j][q] = 0.f;

    float4 pA[4];
    uint4 pBh[2], pBl[2];
#pragma unroll
    for (int it = 0; it < 4; it++) {
        int idx = tid + it * 256;
        int r = idx >> 3, c4 = (idx & 7) * 4;
        pA[it] = (r < mValid) ? *reinterpret_cast<const float4*>(At + (size_t)r * lda + c4)
                              : make_float4(0.f, 0.f, 0.f, 0.f);
    }
#pragma unroll
    for (int it = 0; it < 2; it++) {
        int idx = tid + it * 256;
        int r = idx >> 2, c8 = (idx & 3) * 8;
        pBh[it] = *reinterpret_cast<const uint4*>(Bh_g + (size_t)r * ldb + c8);
        pBl[it] = *reinterpret_cast<const uint4*>(Bl_g + (size_t)r * ldb + c8);
    }

    for (int k0 = 0; k0 < KTOT; k0 += 32) {
#pragma unroll
        for (int it = 0; it < 4; it++) {
            int idx = tid + it * 256;
            int r = idx >> 3, c4 = (idx & 7) * 4;
            int o = r * ASTRIDE + c4;
            float4 v = pA[it];
            uint32_t h0 = pk_hi(v.x, v.y), h1 = pk_hi(v.z, v.w);
            *reinterpret_cast<uint32_t*>(&Ah[o])     = h0;
            *reinterpret_cast<uint32_t*>(&Ah[o + 2]) = h1;
            *reinterpret_cast<uint32_t*>(&Al[o])     = pk_lo(v.x, v.y, h0);
            *reinterpret_cast<uint32_t*>(&Al[o + 2]) = pk_lo(v.z, v.w, h1);
        }
#pragma unroll
        for (int it = 0; it < 2; it++) {
            int idx = tid + it * 256;
            int r = idx >> 2, c8 = (idx & 3) * 8;
            int o = r * ASTRIDE + c8;
            *reinterpret_cast<uint4*>(&Wh[o]) = pBh[it];
            *reinterpret_cast<uint4*>(&Wl[o]) = pBl[it];
        }
        __syncthreads();

        if (k0 + 32 < KTOT) {
#pragma unroll
            for (int it = 0; it < 4; it++) {
                int idx = tid + it * 256;
                int r = idx >> 3, c4 = (idx & 7) * 4;
                pA[it] = (r < mValid) ? *reinterpret_cast<const float4*>(At + (size_t)r * lda + k0 + 32 + c4)
                                      : make_float4(0.f, 0.f, 0.f, 0.f);
            }
#pragma unroll
            for (int it = 0; it < 2; it++) {
                int idx = tid + it * 256;
                int r = idx >> 2, c8 = (idx & 3) * 8;
                pBh[it] = *reinterpret_cast<const uint4*>(Bh_g + (size_t)r * ldb + k0 + 32 + c8);
                pBl[it] = *reinterpret_cast<const uint4*>(Bl_g + (size_t)r * ldb + k0 + 32 + c8);
            }
        }
        mma_section(Ah, Al, Wh, Wl, wm, wn, gid, tig, acc);
        __syncthreads();
    }
}

// ---- tile core: both sides pre-converted bf16 hi/lo (pure-copy staging) -----
__device__ __forceinline__ void hmma_tile_bf(
    const __nv_bfloat16* __restrict__ Ah_g, const __nv_bfloat16* __restrict__ Al_g,
    int lda, int mValid,
    const __nv_bfloat16* __restrict__ Bh_g, const __nv_bfloat16* __restrict__ Bl_g, int ldb,
    int KTOT,
    __nv_bfloat16* Ah, __nv_bfloat16* Al,
    __nv_bfloat16* Wh, __nv_bfloat16* Wl,
    float acc[2][8][4])
{
    const int tid  = threadIdx.x;
    const int w    = tid >> 5;
    const int lane = tid & 31;
    const int gid  = lane >> 2, tig = lane & 3;
    const int wm = w & 3, wn = w >> 2;

#pragma unroll
    for (int i = 0; i < 2; i++)
#pragma unroll
        for (int j = 0; j < 8; j++)
#pragma unroll
            for (int q = 0; q < 4; q++) acc[i][j][q] = 0.f;

    const uint4 z4 = make_uint4(0u, 0u, 0u, 0u);
    uint4 pAh[2], pAl[2], pBh[2], pBl[2];
#pragma unroll
    for (int it = 0; it < 2; it++) {
        int idx = tid + it * 256;
        int r = idx >> 2, c8 = (idx & 3) * 8;
        bool okA = (r < mValid);
        pAh[it] = okA ? *reinterpret_cast<const uint4*>(Ah_g + (size_t)r * lda + c8) : z4;
        pAl[it] = okA ? *reinterpret_cast<const uint4*>(Al_g + (size_t)r * lda + c8) : z4;
        pBh[it] = *reinterpret_cast<const uint4*>(Bh_g + (size_t)r * ldb + c8);
        pBl[it] = *reinterpret_cast<const uint4*>(Bl_g + (size_t)r * ldb + c8);
    }

    for (int k0 = 0; k0 < KTOT; k0 += 32) {
#pragma unroll
        for (int it = 0; it < 2; it++) {
            int idx = tid + it * 256;
            int r = idx >> 2, c8 = (idx & 3) * 8;
            int o = r * ASTRIDE + c8;
            *reinterpret_cast<uint4*>(&Ah[o]) = pAh[it];
            *reinterpret_cast<uint4*>(&Al[o]) = pAl[it];
            *reinterpret_cast<uint4*>(&Wh[o]) = pBh[it];
            *reinterpret_cast<uint4*>(&Wl[o]) = pBl[it];
        }
        __syncthreads();

        if (k0 + 32 < KTOT) {
#pragma unroll
            for (int it = 0; it < 2; it++) {
                int idx = tid + it * 256;
                int r = idx >> 2, c8 = (idx & 3) * 8;
                bool okA = (r < mValid);
                pAh[it] = okA ? *reinterpret_cast<const uint4*>(Ah_g + (size_t)r * lda + k0 + 32 + c8) : z4;
                pAl[it] = okA ? *reinterpret_cast<const uint4*>(Al_g + (size_t)r * lda + k0 + 32 + c8) : z4;
                pBh[it] = *reinterpret_cast<const uint4*>(Bh_g + (size_t)r * ldb + k0 + 32 + c8);
                pBl[it] = *reinterpret_cast<const uint4*>(Bl_g + (size_t)r * ldb + k0 + 32 + c8);
            }
        }
        mma_section(Ah, Al, Wh, Wl, wm, wn, gid, tig, acc);
        __syncthreads();
    }
}

// ---- K1: feat = relu(A @ appear_W^T + b) -> allf (bf16 hi/lo), fused extras -
__global__ __launch_bounds__(256) void k1_appear(
    const float* __restrict__ feat_in,
    const float* __restrict__ score, const float* __restrict__ box,
    const float* __restrict__ origin,
    const float* __restrict__ b, int N)
{
    __shared__ __nv_bfloat16 Ah[128 * ASTRIDE], Al[128 * ASTRIDE];
    __shared__ __nv_bfloat16 Wh[128 * ASTRIDE], Wl[128 * ASTRIDE];
    const int tid  = threadIdx.x;
    const int w    = tid >> 5;
    const int lane = tid & 31;
    const int gid  = lane >> 2, tig = lane & 3;
    const int wm = w & 3, wn = w >> 2;
    const int mBase = blockIdx.x * 128;

    float acc[2][8][4];
    hmma_tile_mixed(feat_in + (size_t)mBase * 1024, 1024, N - mBase,
                    g_apw_h, g_apw_l, 1024, 1024, Ah, Al, Wh, Wl, acc);

#pragma unroll
    for (int mf = 0; mf < 2; mf++)
#pragma unroll
        for (int nf = 0; nf < 8; nf++) {
            int m0 = mBase + wm * 32 + mf * 16 + gid;
            int n0 = wn * 64 + nf * 8 + tig * 2;
            if (m0 < N) {
                float v0 = fmaxf(acc[mf][nf][0] + b[n0],     0.f);
                float v1 = fmaxf(acc[mf][nf][1] + b[n0 + 1], 0.f);
                uint32_t h = pk_hi(v0, v1);
                *reinterpret_cast<uint32_t*>(&g_allf_h[(size_t)m0 * 224 + n0]) = h;
                *reinterpret_cast<uint32_t*>(&g_allf_l[(size_t)m0 * 224 + n0]) = pk_lo(v0, v1, h);
            }
            if (m0 + 8 < N) {
                float v0 = fmaxf(acc[mf][nf][2] + b[n0],     0.f);
                float v1 = fmaxf(acc[mf][nf][3] + b[n0 + 1], 0.f);
                uint32_t h = pk_hi(v0, v1);
                *reinterpret_cast<uint32_t*>(&g_allf_h[(size_t)(m0 + 8) * 224 + n0]) = h;
                *reinterpret_cast<uint32_t*>(&g_allf_l[(size_t)(m0 + 8) * 224 + n0]) = pk_lo(v0, v1, h);
            }
        }
    // extra 96 cols: [score|box|origin] -> bf16 hi/lo pairs
    for (int idx = tid; idx < 128 * 48; idx += 256) {
        int r = idx / 48, jp = idx % 48;
        int jc = jp * 2;
        int m = mBase + r;
        if (m < N) {
            float2 v;
            if (jc < 32)      v = *reinterpret_cast<const float2*>(score  + (size_t)m*32 + jc);
            else if (jc < 64) v = *reinterpret_cast<const float2*>(box    + (size_t)m*32 + jc - 32);
            else              v = *reinterpret_cast<const float2*>(origin + (size_t)m*32 + jc - 64);
            uint32_t h = pk_hi(v.x, v.y);
            *reinterpret_cast<uint32_t*>(&g_allf_h[(size_t)m * 224 + 128 + jc]) = h;
            *reinterpret_cast<uint32_t*>(&g_allf_l[(size_t)m * 224 + 128 + jc]) = pk_lo(v.x, v.y, h);
        }
    }
}

// ---- K2: dec = relu(allf @ feat_W^T + b) -> bf16 hi/lo, K=224 ---------------
__global__ __launch_bounds__(256) void k2_dec(
    const float* __restrict__ b, int N)
{
    __shared__ __nv_bfloat16 Ah[128 * ASTRIDE], Al[128 * ASTRIDE];
    __shared__ __nv_bfloat16 Wh[128 * ASTRIDE], Wl[128 * ASTRIDE];
    const int tid  = threadIdx.x;
    const int w    = tid >> 5;
    const int lane = tid & 31;
    const int gid  = lane >> 2, tig = lane & 3;
    const int wm = w & 3, wn = w >> 2;
    const int mBase = blockIdx.x * 128;

    float acc[2][8][4];
    hmma_tile_bf(g_allf_h + (size_t)mBase * 224, g_allf_l + (size_t)mBase * 224, 224, N - mBase,
                 g_fw_h, g_fw_l, 224, 224, Ah, Al, Wh, Wl, acc);

#pragma unroll
    for (int mf = 0; mf < 2; mf++)
#pragma unroll
        for (int nf = 0; nf < 8; nf++) {
            int m0 = mBase + wm * 32 + mf * 16 + gid;
            int n0 = wn * 64 + nf * 8 + tig * 2;
            if (m0 < N) {
                float v0 = fmaxf(acc[mf][nf][0] + b[n0],     0.f);
                float v1 = fmaxf(acc[mf][nf][1] + b[n0 + 1], 0.f);
                uint32_t h = pk_hi(v0, v1);
                *reinterpret_cast<uint32_t*>(&g_dec_h[(size_t)m0 * 128 + n0]) = h;
                *reinterpret_cast<uint32_t*>(&g_dec_l[(size_t)m0 * 128 + n0]) = pk_lo(v0, v1, h);
            }
            if (m0 + 8 < N) {
                float v0 = fmaxf(acc[mf][nf][2] + b[n0],     0.f);
                float v1 = fmaxf(acc[mf][nf][3] + b[n0 + 1], 0.f);
                uint32_t h = pk_hi(v0, v1);
                *reinterpret_cast<uint32_t*>(&g_dec_h[(size_t)(m0 + 8) * 128 + n0]) = h;
                *reinterpret_cast<uint32_t*>(&g_dec_l[(size_t)(m0 + 8) * 128 + n0]) = pk_lo(v0, v1, h);
            }
        }
}

// ---- K3: Xp = dec @ Wih^T + bih, both dirs, K=128 ---------------------------
__global__ __launch_bounds__(256) void k3_xp(
    const float* __restrict__ bih, int N)
{
    int c = blockIdx.z;
    int start = g_ucl[c];
    int len = g_ucl[c+1] - start;
    int mBase = blockIdx.y * 128;
    if (mBase >= len) return;
    int nBase = blockIdx.x * 128;

    __shared__ __nv_bfloat16 Ah[128 * ASTRIDE], Al[128 * ASTRIDE];
    __shared__ __nv_bfloat16 Wh[128 * ASTRIDE], Wl[128 * ASTRIDE];
    const int tid  = threadIdx.x;
    const int w    = tid >> 5;
    const int lane = tid & 31;
    const int gid  = lane >> 2, tig = lane & 3;
    const int wm = w & 3, wn = w >> 2;

    float acc[2][8][4];
    size_t aoff = (size_t)(start + mBase) * 128;
    size_t boff = ((size_t)c * 768 + nBase) * 128;
    hmma_tile_bf(g_dec_h + aoff, g_dec_l + aoff, 128, len - mBase,
                 g_wih_h + boff, g_wih_l + boff, 128, 128,
                 Ah, Al, Wh, Wl, acc);

    const float* bb = bih + (size_t)c * 768;
    int d   = (nBase >= 384) ? 1 : 0;
    int nl0 = nBase - d * 384;
    float* dst = g_xp + (size_t)d * N * 384 + (size_t)start * 384;
#pragma unroll
    for (int mf = 0; mf < 2; mf++)
#pragma unroll
        for (int nf = 0; nf < 8; nf++) {
            int ml = mBase + wm * 32 + mf * 16 + gid;
            int n0 = wn * 64 + nf * 8 + tig * 2;
            int ng = nBase + n0;
            if (ml < len) {
                dst[(size_t)ml * 384 + nl0 + n0]     = acc[mf][nf][0] + bb[ng];
                dst[(size_t)ml * 384 + nl0 + n0 + 1] = acc[mf][nf][1] + bb[ng + 1];
            }
            if (ml + 8 < len) {
                dst[(size_t)(ml + 8) * 384 + nl0 + n0]     = acc[mf][nf][2] + bb[ng];
                dst[(size_t)(ml + 8) * 384 + nl0 + n0 + 1] = acc[mf][nf][3] + bb[ng + 1];
            }
        }
}

// ---- packed f32x2 FMA + fast tanh -------------------------------------------
__device__ __forceinline__ void fma2(unsigned long long& d,
                                     unsigned long long a,
                                     unsigned long long b) {
    asm("fma.rn.f32x2 %0, %1, %2, %0;" : "+l"(d) : "l"(a), "l"(b));
}
__device__ __forceinline__ float fast_tanh(float x) {
    float y;
    asm("tanh.approx.f32 %0, %1;" : "=f"(y) : "f"(x));
    return y;
}

// ---- K4: sequential GRU, one block per (class, dir), Whh in registers ------
__global__ __launch_bounds__(384, 1) void k4_gru(
    const float* __restrict__ Whh, const float* __restrict__ bhh, int N)
{
    int bid = blockIdx.x;
    int c = (CC - 1) - (bid >> 1);   // longest classes first
    int d = bid & 1;
    int start = g_ucl[c];
    int len = g_ucl[c+1] - start;
    int g = threadIdx.x;

    __shared__ __align__(16) float h_sm[128];
    __shared__ float pre[256];
    __shared__ float gh3[128];
    __shared__ float x3s[128];

    unsigned long long w2[64];
    {
        const ulonglong2* wp = reinterpret_cast<const ulonglong2*>(
            Whh + ((size_t)(c*2 + d) * 384 + g) * 128);
#pragma unroll
        for (int k = 0; k < 32; k++) {
            ulonglong2 v = wp[k];
            w2[2*k]   = v.x;
            w2[2*k+1] = v.y;
        }
    }
    float bg = bhh[(size_t)(c*2 + d) * 384 + g];
    if (g < 128) h_sm[g] = 0.f;
    __syncthreads();

    const float* Xp = g_xp  + (size_t)d * N * 384 + (size_t)start * 384;
    float* Hout     = g_hid + (size_t)d * N * 128 + (size_t)start * 128;

    int j  = (d == 0) ? 0 : len - 1;
    int dj = (d == 0) ? 1 : -1;
    float xg = (len > 0) ? Xp[(size_t)j * 384 + g] : 0.f;

    for (int step = 0; step < len; step++) {
        int jn = j + dj;
        float xn = 0.f;
        if (step + 1 < len) xn = Xp[(size_t)jn * 384 + g];

        unsigned long long a0 = 0ULL, a1 = 0ULL, a2 = 0ULL, a3 = 0ULL;
        const ulonglong2* h2 = reinterpret_cast<const ulonglong2*>(h_sm);
#pragma unroll
        for (int k = 0; k < 32; k += 2) {
            ulonglong2 hv0 = h2[k];
            ulonglong2 hv1 = h2[k+1];
            fma2(a0, w2[2*k],   hv0.x);
            fma2(a1, w2[2*k+1], hv0.y);
            fma2(a2, w2[2*k+2], hv1.x);
            fma2(a3, w2[2*k+3], hv1.y);
        }
        float2 f0 = *reinterpret_cast<float2*>(&a0);
        float2 f1 = *reinterpret_cast<float2*>(&a1);
        float2 f2 = *reinterpret_cast<float2*>(&a2);
        float2 f3 = *reinterpret_cast<float2*>(&a3);
        float gh = ((f0.x + f0.y) + (f1.x + f1.y))
                 + ((f2.x + f2.y) + (f3.x + f3.y)) + bg;

        if (g < 256) pre[g] = xg + gh;
        else { gh3[g - 256] = gh; x3s[g - 256] = xg; }
        __syncthreads();
        if (g < 128) {
            float r  = fmaf(fast_tanh(pre[g]       * 0.5f), 0.5f, 0.5f);
            float z  = fmaf(fast_tanh(pre[128 + g] * 0.5f), 0.5f, 0.5f);
            float u  = x3s[g] + r * gh3[g];
            float nn = fast_tanh(u);
            float hp = h_sm[g];
            float h2v = fmaf(z, hp - nn, nn);
            h_sm[g] = h2v;
            Hout[(size_t)j * 128 + g] = h2v;
        }
        __syncthreads();
        xg = xn;
        j = jn;
    }
}

// ---- K5: out = sigmoid([hf|hb] . out_W + b) --------------------------------
__global__ __launch_bounds__(256) void k5_out(
    const float* __restrict__ outW, const float* __restrict__ outb,
    float* __restrict__ out, int N)
{
    int t = blockIdx.x * blockDim.x + threadIdx.x;
    int row = t >> 5, lane = t & 31;
    if (row >= N) return;
    const float* hf = g_hid + (size_t)row * 128;
    const float* hb = g_hid + (size_t)N * 128 + (size_t)row * 128;
    float s = 0.f;
#pragma unroll
    for (int k = lane; k < 128; k += 32)
        s += outW[k] * hf[k] + outW[128 + k] * hb[k];
#pragma unroll
    for (int o = 16; o > 0; o >>= 1)
        s += __shfl_down_sync(0xffffffffu, s, o);
    if (lane == 0)
        out[row] = __fdividef(1.f, 1.f + __expf(-(s + outb[0])));
}

extern "C" void kernel_launch(void* const* d_in, const int* in_sizes, int n_in,
                              void* d_out, int out_size)
{
    const float* acb_feat  = (const float*)d_in[3];
    const float* acb_score = (const float*)d_in[4];
    const float* acb_box   = (const float*)d_in[5];
    const float* acb_orig  = (const float*)d_in[6];
    const void*  ucl_raw   = d_in[8];
    const float* appear_W  = (const float*)d_in[9];
    const float* appear_b  = (const float*)d_in[10];
    const float* feat_W    = (const float*)d_in[11];
    const float* feat_b    = (const float*)d_in[12];
    const float* gru_Wih   = (const float*)d_in[13];
    const float* gru_Whh   = (const float*)d_in[14];
    const float* gru_bih   = (const float*)d_in[15];
    const float* gru_bhh   = (const float*)d_in[16];
    const float* out_W     = (const float*)d_in[17];
    const float* out_b     = (const float*)d_in[18];

    int N = in_sizes[3] / 1024;
    if (N > MAXN) N = MAXN;
    int Mtiles = (N + 127) / 128;

    k0_ucl<<<1, 96>>>(ucl_raw);
    // weight pre-conversion (fp32 -> bf16 hi/lo)
    {
        __nv_bfloat16 *apw_h, *apw_l, *fw_h, *fw_l, *wih_h, *wih_l;
        cudaGetSymbolAddress((void**)&apw_h, g_apw_h);
        cudaGetSymbolAddress((void**)&apw_l, g_apw_l);
        cudaGetSymbolAddress((void**)&fw_h,  g_fw_h);
        cudaGetSymbolAddress((void**)&fw_l,  g_fw_l);
        cudaGetSymbolAddress((void**)&wih_h, g_wih_h);
        cudaGetSymbolAddress((void**)&wih_l, g_wih_l);
        int n4a = 128 * 1024 / 4;
        kconv<<<(n4a + 255) / 256, 256>>>(appear_W, apw_h, apw_l, n4a);
        int n4f = 128 * 224 / 4;
        kconv<<<(n4f + 255) / 256, 256>>>(feat_W, fw_h, fw_l, n4f);
        int n4w = CC * 768 * 128 / 4;
        kconv<<<(n4w + 255) / 256, 256>>>(gru_Wih, wih_h, wih_l, n4w);
    }
    k1_appear<<<Mtiles, 256>>>(acb_feat, acb_score, acb_box, acb_orig, appear_b, N);
    k2_dec<<<Mtiles, 256>>>(feat_b, N);
    dim3 g3(6, 4, CC);
    k3_xp<<<g3, 256>>>(gru_bih, N);
    k4_gru<<<2 * CC, 384>>>(gru_Whh, gru_bhh, N);
    k5_out<<<(N * 32 + 255) / 256, 256>>>(out_W, out_b, (float*)d_out, N);
}